// round 1
// baseline (speedup 1.0000x reference)
#include <cuda_runtime.h>
#include <cstdint>
#include <cstdio>

// ---------------- problem constants ----------------
#define BB     8
#define NQ_    256
#define DIM_   768
#define KVD_   1024
#define HH     8
#define DH_    64
#define INNER_ 512          // HH*DH
#define TM_    8192         // T*M
#define BNQ    2048         // BB*NQ
#define BTM    65536        // BB*TM
#define LN_EPS 1e-5f

// ---------------- scratch (device globals; no allocs allowed) ----------------
__device__ float g_mu_x[BNQ];
__device__ float g_rs_x[BNQ];
__device__ float g_mu_kv[BTM];
__device__ float g_rs_kv[BTM];
__device__ float g_qbuf[BNQ * INNER_];               // 4 MB
__device__ float g_kvp[(size_t)BTM * 1024];          // 256 MB  (cols 0..511 = K, 512..1023 = V)
__device__ float g_att[BNQ * INNER_];                // 4 MB

// ---------------- helpers ----------------
__device__ __forceinline__ uint32_t f2t(float x) {
    uint32_t r;
    asm("cvt.rna.tf32.f32 %0, %1;" : "=r"(r) : "f"(x));
    return r;
}

__device__ __forceinline__ void mma8(float c[4], const uint32_t a[4],
                                     uint32_t b0, uint32_t b1) {
    asm("mma.sync.aligned.m16n8k8.row.col.f32.tf32.tf32.f32 "
        "{%0,%1,%2,%3}, {%4,%5,%6,%7}, {%8,%9}, {%0,%1,%2,%3};"
        : "+f"(c[0]), "+f"(c[1]), "+f"(c[2]), "+f"(c[3])
        : "r"(a[0]), "r"(a[1]), "r"(a[2]), "r"(a[3]), "r"(b0), "r"(b1));
}

// ---------------- row stats (mean + rstd) ----------------
template <int RL>
__global__ __launch_bounds__(256) void row_stats(const float* __restrict__ X,
                                                 float* __restrict__ mu,
                                                 float* __restrict__ rs) {
    const int row = blockIdx.x;
    const float4* xr = reinterpret_cast<const float4*>(X + (size_t)row * RL);
    float s = 0.f, ss = 0.f;
    for (int i = threadIdx.x; i < RL / 4; i += 256) {
        float4 v = xr[i];
        s  += (v.x + v.y) + (v.z + v.w);
        ss += v.x * v.x + v.y * v.y + v.z * v.z + v.w * v.w;
    }
    #pragma unroll
    for (int o = 16; o; o >>= 1) {
        s  += __shfl_xor_sync(0xffffffffu, s, o);
        ss += __shfl_xor_sync(0xffffffffu, ss, o);
    }
    __shared__ float sh[16];
    const int warp = threadIdx.x >> 5, lane = threadIdx.x & 31;
    if (lane == 0) { sh[warp] = s; sh[warp + 8] = ss; }
    __syncthreads();
    if (threadIdx.x == 0) {
        float S = 0.f, SS = 0.f;
        #pragma unroll
        for (int w = 0; w < 8; w++) { S += sh[w]; SS += sh[w + 8]; }
        const float m = S / (float)RL;
        const float v = SS / (float)RL - m * m;
        mu[row] = m;
        rs[row] = rsqrtf(v + LN_EPS);
    }
}

// ---------------- generic tf32 GEMM: C[M,N] = LN?(A)[M,K] @ B[K,N] ----------------
// Block tile 128x128, k-tile 16, 256 threads (8 warps as 4x2, warp tile 32x64).
#define BM 128
#define BN 128
#define BK 16
#define SAS 136   // sA row stride (k-major), conflict-free fragment loads
#define SBS 136

template <bool LN>
__global__ __launch_bounds__(256, 1) void gemm_tf32(
    const float* __restrict__ A, const float* __restrict__ Bm,
    float* __restrict__ C, int N, int K,
    const float* __restrict__ mu, const float* __restrict__ rs,
    const float* __restrict__ gam, const float* __restrict__ bet) {
    __shared__ uint32_t sA[BK * SAS];
    __shared__ uint32_t sB[BK * SBS];

    const int tid  = threadIdx.x;
    const int warp = tid >> 5, lane = tid & 31;
    const int g = lane >> 2, q = lane & 3;
    const int wm = (warp >> 1) * 32;   // warp row offset
    const int wn = (warp & 1) * 64;    // warp col offset
    const int bm0 = blockIdx.y * BM;
    const int bn0 = blockIdx.x * BN;

    float acc[2][8][4];
    #pragma unroll
    for (int mt = 0; mt < 2; mt++)
        #pragma unroll
        for (int nt = 0; nt < 8; nt++)
            #pragma unroll
            for (int i = 0; i < 4; i++) acc[mt][nt][i] = 0.f;

    const int ar = tid >> 2;          // A row within half-tile (0..63)
    const int ak = (tid & 3) * 4;     // A k-offset (float4)

    for (int kt = 0; kt < K; kt += BK) {
        // --- load A tile (fused LayerNorm), store k-major transposed ---
        #pragma unroll
        for (int p = 0; p < 2; p++) {
            const int r = ar + p * 64;
            const int grow = bm0 + r;
            const float4 v = *reinterpret_cast<const float4*>(
                A + (size_t)grow * K + kt + ak);
            float m_ = 0.f, s_ = 1.f;
            if (LN) { m_ = mu[grow]; s_ = rs[grow]; }
            float vv[4] = {v.x, v.y, v.z, v.w};
            #pragma unroll
            for (int j = 0; j < 4; j++) {
                float f = vv[j];
                if (LN) f = (f - m_) * s_ * gam[kt + ak + j] + bet[kt + ak + j];
                sA[(ak + j) * SAS + r] = f2t(f);
            }
        }
        // --- load B tile ---
        #pragma unroll
        for (int p = 0; p < 2; p++) {
            const int idx = tid + p * 256;       // 512 float4s = 16x128
            const int bk = idx >> 5;
            const int bn = (idx & 31) * 4;
            const float4 v = *reinterpret_cast<const float4*>(
                Bm + (size_t)(kt + bk) * N + bn0 + bn);
            uint32_t* dst = &sB[bk * SBS + bn];
            dst[0] = f2t(v.x); dst[1] = f2t(v.y);
            dst[2] = f2t(v.z); dst[3] = f2t(v.w);
        }
        __syncthreads();

        #pragma unroll
        for (int kk = 0; kk < BK; kk += 8) {
            uint32_t af[2][4];
            #pragma unroll
            for (int mt = 0; mt < 2; mt++) {
                const int mr = wm + mt * 16 + g;
                af[mt][0] = sA[(kk + q) * SAS + mr];
                af[mt][1] = sA[(kk + q) * SAS + mr + 8];
                af[mt][2] = sA[(kk + q + 4) * SAS + mr];
                af[mt][3] = sA[(kk + q + 4) * SAS + mr + 8];
            }
            #pragma unroll
            for (int nt = 0; nt < 8; nt++) {
                const int nc = wn + nt * 8 + g;
                const uint32_t b0 = sB[(kk + q) * SBS + nc];
                const uint32_t b1 = sB[(kk + q + 4) * SBS + nc];
                mma8(acc[0][nt], af[0], b0, b1);
                mma8(acc[1][nt], af[1], b0, b1);
            }
        }
        __syncthreads();
    }

    #pragma unroll
    for (int mt = 0; mt < 2; mt++)
        #pragma unroll
        for (int nt = 0; nt < 8; nt++) {
            const int r0 = bm0 + wm + mt * 16 + g;
            const int c0 = bn0 + wn + nt * 8 + q * 2;
            *reinterpret_cast<float2*>(C + (size_t)r0 * N + c0) =
                make_float2(acc[mt][nt][0], acc[mt][nt][1]);
            *reinterpret_cast<float2*>(C + (size_t)(r0 + 8) * N + c0) =
                make_float2(acc[mt][nt][2], acc[mt][nt][3]);
        }
}

// ---------------- flash attention ----------------
// grid (64 bh, 2 qtiles), 256 threads = 8 warps, 16 q-rows per warp.
#define JC  64     // j chunk
#define AST 68     // smem row stride

__global__ __launch_bounds__(256, 1) void attention_kernel(
    const float* __restrict__ Q, const float* __restrict__ KV,
    float* __restrict__ O) {
    extern __shared__ uint32_t sm[];
    uint32_t* Ks = sm;                    // [64][68]
    uint32_t* Vs = Ks + JC * AST;         // [64][68]
    uint32_t* Ps = Vs + JC * AST;         // [128][68]

    const int bh = blockIdx.x;
    const int b = bh >> 3, h = bh & 7;
    const int q0 = blockIdx.y * 128;
    const int tid = threadIdx.x, warp = tid >> 5, lane = tid & 31;
    const int g = lane >> 2, q = lane & 3;
    const float scale = 0.125f;   // DH^-0.5

    // Q fragments resident in registers (16 rows per warp, K=64 -> 8 k-steps)
    uint32_t qa[8][4];
    const int qrow0 = b * NQ_ + q0 + warp * 16;
    const float* Qb = Q + (size_t)qrow0 * INNER_ + h * DH_;
    #pragma unroll
    for (int kk = 0; kk < 8; kk++) {
        qa[kk][0] = f2t(Qb[(size_t)g * INNER_ + kk * 8 + q] * scale);
        qa[kk][1] = f2t(Qb[(size_t)(g + 8) * INNER_ + kk * 8 + q] * scale);
        qa[kk][2] = f2t(Qb[(size_t)g * INNER_ + kk * 8 + q + 4] * scale);
        qa[kk][3] = f2t(Qb[(size_t)(g + 8) * INNER_ + kk * 8 + q + 4] * scale);
    }

    float oacc[8][4];
    #pragma unroll
    for (int nt = 0; nt < 8; nt++)
        #pragma unroll
        for (int i = 0; i < 4; i++) oacc[nt][i] = 0.f;
    float mrow0 = -1e30f, mrow1 = -1e30f;
    float lrow0 = 0.f, lrow1 = 0.f;

    const float* Kbase = KV + (size_t)(b * TM_) * 1024 + h * DH_;
    const float* Vbase = Kbase + INNER_;

    for (int j0 = 0; j0 < TM_; j0 += JC) {
        // cooperative load of K,V chunk (64 x 64 each), convert to tf32
        #pragma unroll
        for (int p = 0; p < 4; p++) {
            const int idx = tid + p * 256;   // 1024 float4s per matrix
            const int jj = idx >> 4;
            const int d4 = (idx & 15) * 4;
            const float4 kv4 = *reinterpret_cast<const float4*>(
                Kbase + (size_t)(j0 + jj) * 1024 + d4);
            uint32_t* kd = &Ks[jj * AST + d4];
            kd[0] = f2t(kv4.x); kd[1] = f2t(kv4.y);
            kd[2] = f2t(kv4.z); kd[3] = f2t(kv4.w);
            const float4 vv4 = *reinterpret_cast<const float4*>(
                Vbase + (size_t)(j0 + jj) * 1024 + d4);
            uint32_t* vd = &Vs[jj * AST + d4];
            vd[0] = f2t(vv4.x); vd[1] = f2t(vv4.y);
            vd[2] = f2t(vv4.z); vd[3] = f2t(vv4.w);
        }
        __syncthreads();

        // S = Q @ K^T  (warp: 16 x 64)
        float sacc[8][4];
        #pragma unroll
        for (int nt = 0; nt < 8; nt++)
            #pragma unroll
            for (int i = 0; i < 4; i++) sacc[nt][i] = 0.f;
        #pragma unroll
        for (int kk = 0; kk < 8; kk++) {
            #pragma unroll
            for (int nt = 0; nt < 8; nt++) {
                const uint32_t b0 = Ks[(nt * 8 + g) * AST + kk * 8 + q];
                const uint32_t b1 = Ks[(nt * 8 + g) * AST + kk * 8 + q + 4];
                mma8(sacc[nt], qa[kk], b0, b1);
            }
        }

        // online softmax (rows g and g+8; quad owns the 64 cols)
        float mn0 = mrow0, mn1 = mrow1;
        #pragma unroll
        for (int nt = 0; nt < 8; nt++) {
            mn0 = fmaxf(mn0, fmaxf(sacc[nt][0], sacc[nt][1]));
            mn1 = fmaxf(mn1, fmaxf(sacc[nt][2], sacc[nt][3]));
        }
        #pragma unroll
        for (int o = 1; o < 4; o <<= 1) {
            mn0 = fmaxf(mn0, __shfl_xor_sync(0xffffffffu, mn0, o));
            mn1 = fmaxf(mn1, __shfl_xor_sync(0xffffffffu, mn1, o));
        }
        const float al0 = __expf(mrow0 - mn0);
        const float al1 = __expf(mrow1 - mn1);
        float ls0 = 0.f, ls1 = 0.f;
        #pragma unroll
        for (int nt = 0; nt < 8; nt++) {
            sacc[nt][0] = __expf(sacc[nt][0] - mn0);
            sacc[nt][1] = __expf(sacc[nt][1] - mn0);
            sacc[nt][2] = __expf(sacc[nt][2] - mn1);
            sacc[nt][3] = __expf(sacc[nt][3] - mn1);
            ls0 += sacc[nt][0] + sacc[nt][1];
            ls1 += sacc[nt][2] + sacc[nt][3];
        }
        #pragma unroll
        for (int o = 1; o < 4; o <<= 1) {
            ls0 += __shfl_xor_sync(0xffffffffu, ls0, o);
            ls1 += __shfl_xor_sync(0xffffffffu, ls1, o);
        }
        lrow0 = lrow0 * al0 + ls0;
        lrow1 = lrow1 * al1 + ls1;
        mrow0 = mn0; mrow1 = mn1;
        #pragma unroll
        for (int nt = 0; nt < 8; nt++) {
            oacc[nt][0] *= al0; oacc[nt][1] *= al0;
            oacc[nt][2] *= al1; oacc[nt][3] *= al1;
        }

        // stash P (tf32) in warp-private smem region
        #pragma unroll
        for (int nt = 0; nt < 8; nt++) {
            uint32_t* pd = &Ps[(warp * 16 + g) * AST + nt * 8 + q * 2];
            pd[0] = f2t(sacc[nt][0]); pd[1] = f2t(sacc[nt][1]);
            uint32_t* pd2 = &Ps[(warp * 16 + g + 8) * AST + nt * 8 + q * 2];
            pd2[0] = f2t(sacc[nt][2]); pd2[1] = f2t(sacc[nt][3]);
        }
        __syncwarp();

        // O += P @ V
        #pragma unroll
        for (int kk = 0; kk < 8; kk++) {
            uint32_t af[4];
            af[0] = Ps[(warp * 16 + g) * AST + kk * 8 + q];
            af[1] = Ps[(warp * 16 + g + 8) * AST + kk * 8 + q];
            af[2] = Ps[(warp * 16 + g) * AST + kk * 8 + q + 4];
            af[3] = Ps[(warp * 16 + g + 8) * AST + kk * 8 + q + 4];
            #pragma unroll
            for (int nt = 0; nt < 8; nt++) {
                const uint32_t b0 = Vs[(kk * 8 + q) * AST + nt * 8 + g];
                const uint32_t b1 = Vs[(kk * 8 + q + 4) * AST + nt * 8 + g];
                mma8(oacc[nt], af, b0, b1);
            }
        }
        __syncthreads();
    }

    // epilogue: normalize and write [b, nq, h*DH + d]
    const float inv0 = 1.f / lrow0;
    const float inv1 = 1.f / lrow1;
    float* Ob = O + (size_t)qrow0 * INNER_ + h * DH_;
    #pragma unroll
    for (int nt = 0; nt < 8; nt++) {
        const int c0 = nt * 8 + q * 2;
        *reinterpret_cast<float2*>(Ob + (size_t)g * INNER_ + c0) =
            make_float2(oacc[nt][0] * inv0, oacc[nt][1] * inv0);
        *reinterpret_cast<float2*>(Ob + (size_t)(g + 8) * INNER_ + c0) =
            make_float2(oacc[nt][2] * inv1, oacc[nt][3] * inv1);
    }
}

// ---------------- launch ----------------
extern "C" void kernel_launch(void* const* d_in, const int* in_sizes, int n_in,
                              void* d_out, int out_size) {
    const float* x    = (const float*)d_in[0];
    const float* k_v  = (const float*)d_in[1];
    const float* g_q  = (const float*)d_in[2];
    const float* b_q  = (const float*)d_in[3];
    const float* g_kv = (const float*)d_in[4];
    const float* b_kv = (const float*)d_in[5];
    const float* Wq   = (const float*)d_in[6];
    const float* Wkv  = (const float*)d_in[7];
    const float* Wo   = (const float*)d_in[8];
    float* out = (float*)d_out;

    float *mu_x, *rs_x, *mu_kv, *rs_kv, *qbuf, *kvp, *att;
    cudaGetSymbolAddress((void**)&mu_x,  g_mu_x);
    cudaGetSymbolAddress((void**)&rs_x,  g_rs_x);
    cudaGetSymbolAddress((void**)&mu_kv, g_mu_kv);
    cudaGetSymbolAddress((void**)&rs_kv, g_rs_kv);
    cudaGetSymbolAddress((void**)&qbuf,  g_qbuf);
    cudaGetSymbolAddress((void**)&kvp,   g_kvp);
    cudaGetSymbolAddress((void**)&att,   g_att);

    // 1) row stats for both LayerNorms
    row_stats<DIM_><<<BNQ, 256>>>(x, mu_x, rs_x);
    row_stats<KVD_><<<BTM, 256>>>(k_v, mu_kv, rs_kv);

    // 2) q = LN(x) @ Wq   [2048,768]x[768,512]
    gemm_tf32<true><<<dim3(INNER_ / BN, BNQ / BM), 256>>>(
        x, Wq, qbuf, INNER_, DIM_, mu_x, rs_x, g_q, b_q);

    // 3) kv = LN(k_v) @ Wkv   [65536,1024]x[1024,1024]
    gemm_tf32<true><<<dim3(1024 / BN, BTM / BM), 256>>>(
        k_v, Wkv, kvp, 1024, KVD_, mu_kv, rs_kv, g_kv, b_kv);

    // 4) flash attention
    static const int ATT_SMEM = (JC + JC + 128) * AST * 4;  // 69632 B
    cudaFuncSetAttribute(attention_kernel,
                         cudaFuncAttributeMaxDynamicSharedMemorySize, ATT_SMEM);
    attention_kernel<<<dim3(BB * HH, NQ_ / 128), 256, ATT_SMEM>>>(qbuf, kvp, att);

    // 5) out = att @ Wo   [2048,512]x[512,768]
    gemm_tf32<false><<<dim3(DIM_ / BN, BNQ / BM), 256>>>(
        att, Wo, out, DIM_, INNER_, nullptr, nullptr, nullptr, nullptr);
}

// round 2
// speedup vs baseline: 1.8066x; 1.8066x over previous
#include <cuda_runtime.h>
#include <cstdint>

// ---------------- problem constants ----------------
#define BB     8
#define NQ_    256
#define DIM_   768
#define KVD_   1024
#define HH     8
#define DH_    64
#define INNER_ 512
#define TM_    8192
#define BNQ    2048
#define BTM    65536
#define LN_EPS 1e-5f

// ---------------- scratch (device globals) ----------------
__device__ uint32_t g_xn[BNQ * DIM_];                    // LN(x) as tf32 bits
__device__ uint32_t g_kvn[(size_t)BTM * KVD_];           // LN(k_v) as tf32 bits (256MB)
__device__ uint32_t g_wq[DIM_ * INNER_];
__device__ uint32_t g_wkv[KVD_ * 2 * INNER_];
__device__ uint32_t g_wo[INNER_ * DIM_];
__device__ uint32_t g_qbuf[BNQ * INNER_];                // q*scale, tf32 bits
__device__ uint32_t g_kvp[(size_t)BTM * 1024];           // K|V proj, tf32 bits (256MB)
__device__ uint32_t g_att[BNQ * INNER_];                 // attn out, tf32 bits

// ---------------- helpers ----------------
__device__ __forceinline__ uint32_t f2t(float x) {
    uint32_t r;
    asm("cvt.rna.tf32.f32 %0, %1;" : "=r"(r) : "f"(x));
    return r;
}

__device__ __forceinline__ void mma8(float c[4], const uint32_t a[4],
                                     uint32_t b0, uint32_t b1) {
    asm("mma.sync.aligned.m16n8k8.row.col.f32.tf32.tf32.f32 "
        "{%0,%1,%2,%3}, {%4,%5,%6,%7}, {%8,%9}, {%0,%1,%2,%3};"
        : "+f"(c[0]), "+f"(c[1]), "+f"(c[2]), "+f"(c[3])
        : "r"(a[0]), "r"(a[1]), "r"(a[2]), "r"(a[3]), "r"(b0), "r"(b1));
}

__device__ __forceinline__ void cpa(uint32_t dst, const void* src) {
    asm volatile("cp.async.cg.shared.global [%0], [%1], 16;" :: "r"(dst), "l"(src));
}
#define CP_COMMIT asm volatile("cp.async.commit_group;")
#define CP_WAIT1  asm volatile("cp.async.wait_group 1;")
#define CP_WAIT2  asm volatile("cp.async.wait_group 2;")

// ---------------- fused LayerNorm + tf32 convert ----------------
template <int RL>
__global__ __launch_bounds__(256) void ln_conv(const float* __restrict__ X,
                                               const float* __restrict__ gam,
                                               const float* __restrict__ bet,
                                               uint32_t* __restrict__ Y) {
    const int row = blockIdx.x;
    const int i = threadIdx.x;
    const bool act = i < RL / 4;
    float4 v = make_float4(0.f, 0.f, 0.f, 0.f);
    if (act) v = reinterpret_cast<const float4*>(X + (size_t)row * RL)[i];
    float s  = (v.x + v.y) + (v.z + v.w);
    float ss = v.x * v.x + v.y * v.y + v.z * v.z + v.w * v.w;
    #pragma unroll
    for (int o = 16; o; o >>= 1) {
        s  += __shfl_xor_sync(0xffffffffu, s, o);
        ss += __shfl_xor_sync(0xffffffffu, ss, o);
    }
    __shared__ float sh[16];
    __shared__ float st[2];
    const int w = i >> 5, l = i & 31;
    if (l == 0) { sh[w] = s; sh[w + 8] = ss; }
    __syncthreads();
    if (i == 0) {
        float S = 0.f, SS = 0.f;
        #pragma unroll
        for (int k = 0; k < 8; k++) { S += sh[k]; SS += sh[k + 8]; }
        const float m = S / (float)RL;
        st[0] = m;
        st[1] = rsqrtf(SS / (float)RL - m * m + LN_EPS);
    }
    __syncthreads();
    if (act) {
        const float m = st[0], r = st[1];
        const float4 gv = reinterpret_cast<const float4*>(gam)[i];
        const float4 bv = reinterpret_cast<const float4*>(bet)[i];
        uint4 o;
        o.x = f2t((v.x - m) * r * gv.x + bv.x);
        o.y = f2t((v.y - m) * r * gv.y + bv.y);
        o.z = f2t((v.z - m) * r * gv.z + bv.z);
        o.w = f2t((v.w - m) * r * gv.w + bv.w);
        reinterpret_cast<uint4*>(Y + (size_t)row * RL)[i] = o;
    }
}

// ---------------- weight -> tf32 bits ----------------
__global__ void wconv(const float4* __restrict__ X, uint4* __restrict__ Y, int n4) {
    const int i = blockIdx.x * blockDim.x + threadIdx.x;
    if (i < n4) {
        const float4 v = X[i];
        uint4 o;
        o.x = f2t(v.x); o.y = f2t(v.y); o.z = f2t(v.z); o.w = f2t(v.w);
        Y[i] = o;
    }
}

// ---------------- pipelined tf32 GEMM: C = (A @ B) * alpha ----------------
// A[M,K], B[K,N] already tf32 bits. 128x128x16 tiles, 3-stage cp.async.
#define BM 128
#define BN 128
#define BK 16
#define STG 3
#define SAS 20            // A smem row stride (row-major [BM][BK+pad])
#define SBS 136           // B smem row stride ([BK][BN+pad])
#define ASTG (BM * SAS)   // 2560
#define BSTG (BK * SBS)   // 2176
#define GEMM_SMEM (STG * (ASTG + BSTG) * 4)   // 56832 B

template <bool OTF>
__global__ __launch_bounds__(256, 2) void gemm_tf32(
    const uint32_t* __restrict__ A, const uint32_t* __restrict__ B,
    void* __restrict__ Cv, int N, int K, float alpha) {
    extern __shared__ uint32_t smg[];
    uint32_t* sA = smg;
    uint32_t* sB = smg + STG * ASTG;
    const uint32_t sA_b = (uint32_t)__cvta_generic_to_shared(sA);
    const uint32_t sB_b = (uint32_t)__cvta_generic_to_shared(sB);

    const int tid = threadIdx.x;
    const int warp = tid >> 5, lane = tid & 31;
    const int g = lane >> 2, q = lane & 3;
    const int wm = (warp >> 1) * 32;
    const int wn = (warp & 1) * 64;
    const int bm0 = blockIdx.y * BM;
    const int bn0 = blockIdx.x * BN;
    const uint32_t* Ab = A + (size_t)bm0 * K;

    auto issue = [&](int stage, int kt) {
        #pragma unroll
        for (int c = 0; c < 2; c++) {
            const int cid = tid + c * 256;
            const int row = cid >> 2, kq = (cid & 3) << 2;
            cpa(sA_b + (uint32_t)(stage * ASTG + row * SAS + kq) * 4,
                Ab + (size_t)row * K + kt + kq);
            const int brow = cid >> 5, bn = (cid & 31) << 2;
            cpa(sB_b + (uint32_t)(stage * BSTG + brow * SBS + bn) * 4,
                B + (size_t)(kt + brow) * N + bn0 + bn);
        }
    };

    float acc[2][8][4];
    #pragma unroll
    for (int mt = 0; mt < 2; mt++)
        #pragma unroll
        for (int nt = 0; nt < 8; nt++)
            #pragma unroll
            for (int i = 0; i < 4; i++) acc[mt][nt][i] = 0.f;

    const int nk = K / BK;
    issue(0, 0);  CP_COMMIT;
    issue(1, BK); CP_COMMIT;

    for (int t = 0; t < nk; t++) {
        if (t + 2 < nk) issue((t + 2) % STG, (t + 2) * BK);
        CP_COMMIT;
        CP_WAIT2;
        __syncthreads();
        const uint32_t* cA = sA + (t % STG) * ASTG;
        const uint32_t* cB = sB + (t % STG) * BSTG;
        #pragma unroll
        for (int kk = 0; kk < BK; kk += 8) {
            uint32_t af[2][4];
            #pragma unroll
            for (int mt = 0; mt < 2; mt++) {
                const int mr = wm + mt * 16 + g;
                af[mt][0] = cA[mr * SAS + kk + q];
                af[mt][1] = cA[(mr + 8) * SAS + kk + q];
                af[mt][2] = cA[mr * SAS + kk + q + 4];
                af[mt][3] = cA[(mr + 8) * SAS + kk + q + 4];
            }
            #pragma unroll
            for (int nt = 0; nt < 8; nt++) {
                const int nc = wn + nt * 8 + g;
                const uint32_t b0 = cB[(kk + q) * SBS + nc];
                const uint32_t b1 = cB[(kk + q + 4) * SBS + nc];
                mma8(acc[0][nt], af[0], b0, b1);
                mma8(acc[1][nt], af[1], b0, b1);
            }
        }
        __syncthreads();
    }

    #pragma unroll
    for (int mt = 0; mt < 2; mt++)
        #pragma unroll
        for (int nt = 0; nt < 8; nt++) {
            const int r0 = bm0 + wm + mt * 16 + g;
            const int c0 = bn0 + wn + nt * 8 + q * 2;
            if (OTF) {
                uint32_t* C = (uint32_t*)Cv;
                uint2 v0 = make_uint2(f2t(acc[mt][nt][0] * alpha), f2t(acc[mt][nt][1] * alpha));
                uint2 v1 = make_uint2(f2t(acc[mt][nt][2] * alpha), f2t(acc[mt][nt][3] * alpha));
                *reinterpret_cast<uint2*>(C + (size_t)r0 * N + c0) = v0;
                *reinterpret_cast<uint2*>(C + (size_t)(r0 + 8) * N + c0) = v1;
            } else {
                float* C = (float*)Cv;
                *reinterpret_cast<float2*>(C + (size_t)r0 * N + c0) =
                    make_float2(acc[mt][nt][0] * alpha, acc[mt][nt][1] * alpha);
                *reinterpret_cast<float2*>(C + (size_t)(r0 + 8) * N + c0) =
                    make_float2(acc[mt][nt][2] * alpha, acc[mt][nt][3] * alpha);
            }
        }
}

// ---------------- flash attention (double-buffered cp.async) ----------------
#define JC  64
#define AST 68
#define KOFF(buf) ((buf) * JC * AST)
#define VOFF(buf) (2 * JC * AST + (buf) * JC * AST)
#define POFF (4 * JC * AST)
#define ATT_SMEM ((4 * JC * AST + 128 * AST) * 4)   // 104448 B

__global__ __launch_bounds__(256, 1) void attention_kernel(
    const uint32_t* __restrict__ Q, const uint32_t* __restrict__ KV,
    uint32_t* __restrict__ O) {
    extern __shared__ uint32_t sm[];
    const uint32_t s_b = (uint32_t)__cvta_generic_to_shared(sm);

    const int bh = blockIdx.x;
    const int b = bh >> 3, h = bh & 7;
    const int q0 = blockIdx.y * 128;
    const int tid = threadIdx.x, warp = tid >> 5, lane = tid & 31;
    const int g = lane >> 2, q = lane & 3;

    const uint32_t* Kg = KV + (size_t)(b * TM_) * 1024 + h * DH_;
    const uint32_t* Vg = Kg + INNER_;

    auto issue = [&](int buf, int j0) {
        #pragma unroll
        for (int p = 0; p < 4; p++) {
            const int cid = tid + p * 256;
            const int jj = cid >> 4, d4 = (cid & 15) << 2;
            cpa(s_b + (uint32_t)(KOFF(buf) + jj * AST + d4) * 4,
                Kg + (size_t)(j0 + jj) * 1024 + d4);
            cpa(s_b + (uint32_t)(VOFF(buf) + jj * AST + d4) * 4,
                Vg + (size_t)(j0 + jj) * 1024 + d4);
        }
    };

    // Q fragments resident (pre-scaled tf32 bits)
    uint32_t qa[8][4];
    const int qrow0 = b * NQ_ + q0 + warp * 16;
    const uint32_t* Qb = Q + (size_t)qrow0 * INNER_ + h * DH_;
    #pragma unroll
    for (int kk = 0; kk < 8; kk++) {
        qa[kk][0] = Qb[(size_t)g * INNER_ + kk * 8 + q];
        qa[kk][1] = Qb[(size_t)(g + 8) * INNER_ + kk * 8 + q];
        qa[kk][2] = Qb[(size_t)g * INNER_ + kk * 8 + q + 4];
        qa[kk][3] = Qb[(size_t)(g + 8) * INNER_ + kk * 8 + q + 4];
    }

    float oacc[8][4];
    #pragma unroll
    for (int nt = 0; nt < 8; nt++)
        #pragma unroll
        for (int i = 0; i < 4; i++) oacc[nt][i] = 0.f;
    float mrow0 = -1e30f, mrow1 = -1e30f;
    float lrow0 = 0.f, lrow1 = 0.f;

    const int NC = TM_ / JC;
    issue(0, 0); CP_COMMIT;

    for (int jc = 0; jc < NC; jc++) {
        const int buf = jc & 1;
        if (jc + 1 < NC) issue(buf ^ 1, (jc + 1) * JC);
        CP_COMMIT;
        CP_WAIT1;
        __syncthreads();

        const uint32_t* Ks = sm + KOFF(buf);
        const uint32_t* Vs = sm + VOFF(buf);
        uint32_t* Ps = sm + POFF;

        // S = Q @ K^T  (warp: 16 x 64)
        float sacc[8][4];
        #pragma unroll
        for (int nt = 0; nt < 8; nt++)
            #pragma unroll
            for (int i = 0; i < 4; i++) sacc[nt][i] = 0.f;
        #pragma unroll
        for (int kk = 0; kk < 8; kk++) {
            #pragma unroll
            for (int nt = 0; nt < 8; nt++) {
                const uint32_t b0 = Ks[(nt * 8 + g) * AST + kk * 8 + q];
                const uint32_t b1 = Ks[(nt * 8 + g) * AST + kk * 8 + q + 4];
                mma8(sacc[nt], qa[kk], b0, b1);
            }
        }

        // online softmax
        float mn0 = mrow0, mn1 = mrow1;
        #pragma unroll
        for (int nt = 0; nt < 8; nt++) {
            mn0 = fmaxf(mn0, fmaxf(sacc[nt][0], sacc[nt][1]));
            mn1 = fmaxf(mn1, fmaxf(sacc[nt][2], sacc[nt][3]));
        }
        #pragma unroll
        for (int o = 1; o < 4; o <<= 1) {
            mn0 = fmaxf(mn0, __shfl_xor_sync(0xffffffffu, mn0, o));
            mn1 = fmaxf(mn1, __shfl_xor_sync(0xffffffffu, mn1, o));
        }
        const float al0 = __expf(mrow0 - mn0);
        const float al1 = __expf(mrow1 - mn1);
        float ls0 = 0.f, ls1 = 0.f;
        #pragma unroll
        for (int nt = 0; nt < 8; nt++) {
            sacc[nt][0] = __expf(sacc[nt][0] - mn0);
            sacc[nt][1] = __expf(sacc[nt][1] - mn0);
            sacc[nt][2] = __expf(sacc[nt][2] - mn1);
            sacc[nt][3] = __expf(sacc[nt][3] - mn1);
            ls0 += sacc[nt][0] + sacc[nt][1];
            ls1 += sacc[nt][2] + sacc[nt][3];
        }
        #pragma unroll
        for (int o = 1; o < 4; o <<= 1) {
            ls0 += __shfl_xor_sync(0xffffffffu, ls0, o);
            ls1 += __shfl_xor_sync(0xffffffffu, ls1, o);
        }
        lrow0 = lrow0 * al0 + ls0;
        lrow1 = lrow1 * al1 + ls1;
        mrow0 = mn0; mrow1 = mn1;
        #pragma unroll
        for (int nt = 0; nt < 8; nt++) {
            oacc[nt][0] *= al0; oacc[nt][1] *= al0;
            oacc[nt][2] *= al1; oacc[nt][3] *= al1;
        }

        // stash P (tf32) in warp-private smem region
        #pragma unroll
        for (int nt = 0; nt < 8; nt++) {
            uint32_t* pd = &Ps[(warp * 16 + g) * AST + nt * 8 + q * 2];
            pd[0] = f2t(sacc[nt][0]); pd[1] = f2t(sacc[nt][1]);
            uint32_t* pd2 = &Ps[(warp * 16 + g + 8) * AST + nt * 8 + q * 2];
            pd2[0] = f2t(sacc[nt][2]); pd2[1] = f2t(sacc[nt][3]);
        }
        __syncwarp();

        // O += P @ V
        #pragma unroll
        for (int kk = 0; kk < 8; kk++) {
            uint32_t af[4];
            af[0] = Ps[(warp * 16 + g) * AST + kk * 8 + q];
            af[1] = Ps[(warp * 16 + g + 8) * AST + kk * 8 + q];
            af[2] = Ps[(warp * 16 + g) * AST + kk * 8 + q + 4];
            af[3] = Ps[(warp * 16 + g + 8) * AST + kk * 8 + q + 4];
            #pragma unroll
            for (int nt = 0; nt < 8; nt++) {
                const uint32_t b0 = Vs[(kk * 8 + q) * AST + nt * 8 + g];
                const uint32_t b1 = Vs[(kk * 8 + q + 4) * AST + nt * 8 + g];
                mma8(oacc[nt], af, b0, b1);
            }
        }
        __syncthreads();
    }

    // epilogue: normalize, convert to tf32 bits for final GEMM
    const float inv0 = 1.f / lrow0;
    const float inv1 = 1.f / lrow1;
    uint32_t* Ob = O + (size_t)qrow0 * INNER_ + h * DH_;
    #pragma unroll
    for (int nt = 0; nt < 8; nt++) {
        const int c0 = nt * 8 + q * 2;
        Ob[(size_t)g * INNER_ + c0]     = f2t(oacc[nt][0] * inv0);
        Ob[(size_t)g * INNER_ + c0 + 1] = f2t(oacc[nt][1] * inv0);
        Ob[(size_t)(g + 8) * INNER_ + c0]     = f2t(oacc[nt][2] * inv1);
        Ob[(size_t)(g + 8) * INNER_ + c0 + 1] = f2t(oacc[nt][3] * inv1);
    }
}

// ---------------- launch ----------------
extern "C" void kernel_launch(void* const* d_in, const int* in_sizes, int n_in,
                              void* d_out, int out_size) {
    const float* x    = (const float*)d_in[0];
    const float* k_v  = (const float*)d_in[1];
    const float* g_q  = (const float*)d_in[2];
    const float* b_q  = (const float*)d_in[3];
    const float* g_kv = (const float*)d_in[4];
    const float* b_kv = (const float*)d_in[5];
    const float* Wq   = (const float*)d_in[6];
    const float* Wkv  = (const float*)d_in[7];
    const float* Wo   = (const float*)d_in[8];
    float* out = (float*)d_out;

    uint32_t *xn, *kvn, *wq, *wkv, *wo, *qbuf, *kvp, *att;
    cudaGetSymbolAddress((void**)&xn,   g_xn);
    cudaGetSymbolAddress((void**)&kvn,  g_kvn);
    cudaGetSymbolAddress((void**)&wq,   g_wq);
    cudaGetSymbolAddress((void**)&wkv,  g_wkv);
    cudaGetSymbolAddress((void**)&wo,   g_wo);
    cudaGetSymbolAddress((void**)&qbuf, g_qbuf);
    cudaGetSymbolAddress((void**)&kvp,  g_kvp);
    cudaGetSymbolAddress((void**)&att,  g_att);

    cudaFuncSetAttribute(gemm_tf32<true>,
                         cudaFuncAttributeMaxDynamicSharedMemorySize, GEMM_SMEM);
    cudaFuncSetAttribute(gemm_tf32<false>,
                         cudaFuncAttributeMaxDynamicSharedMemorySize, GEMM_SMEM);
    cudaFuncSetAttribute(attention_kernel,
                         cudaFuncAttributeMaxDynamicSharedMemorySize, ATT_SMEM);

    // 1) LayerNorm + tf32 convert
    ln_conv<DIM_><<<BNQ, 256>>>(x, g_q, b_q, xn);
    ln_conv<KVD_><<<BTM, 256>>>(k_v, g_kv, b_kv, kvn);

    // weights -> tf32 bits
    wconv<<<(DIM_ * INNER_ / 4 + 255) / 256, 256>>>((const float4*)Wq,  (uint4*)wq,  DIM_ * INNER_ / 4);
    wconv<<<(KVD_ * 1024 / 4 + 255) / 256, 256>>>((const float4*)Wkv, (uint4*)wkv, KVD_ * 1024 / 4);
    wconv<<<(INNER_ * DIM_ / 4 + 255) / 256, 256>>>((const float4*)Wo,  (uint4*)wo,  INNER_ * DIM_ / 4);

    // 2) q = LN(x) @ Wq * scale   [2048,768]x[768,512]
    gemm_tf32<true><<<dim3(INNER_ / BN, BNQ / BM), 256, GEMM_SMEM>>>(
        xn, wq, qbuf, INNER_, DIM_, 0.125f);

    // 3) kv = LN(k_v) @ Wkv   [65536,1024]x[1024,1024]
    gemm_tf32<true><<<dim3(1024 / BN, BTM / BM), 256, GEMM_SMEM>>>(
        kvn, wkv, kvp, 1024, KVD_, 1.f);

    // 4) flash attention
    attention_kernel<<<dim3(BB * HH, NQ_ / 128), 256, ATT_SMEM>>>(qbuf, kvp, att);

    // 5) out = att @ Wo   [2048,512]x[512,768]
    gemm_tf32<false><<<dim3(DIM_ / BN, BNQ / BM), 256, GEMM_SMEM>>>(
        att, wo, out, DIM_, INNER_, 1.f);
}

// round 4
// speedup vs baseline: 3.3654x; 1.8629x over previous
#include <cuda_runtime.h>
#include <cuda_fp16.h>
#include <cstdint>

// ---------------- problem constants ----------------
#define BB     8
#define NQ_    256
#define DIM_   768
#define KVD_   1024
#define HH     8
#define DH_    64
#define INNER_ 512
#define TM_    8192
#define BNQ    2048
#define BTM    65536
#define LN_EPS 1e-5f

// ---------------- scratch (device globals) ----------------
__device__ __half g_xn[BNQ * DIM_];                 // LN(x) fp16
__device__ __half g_kvn[(size_t)BTM * KVD_];        // LN(k_v) fp16 (128MB)
__device__ __half g_wqT[INNER_ * DIM_];             // Wq^T [512][768]
__device__ __half g_wkvT[1024 * KVD_];              // Wkv^T [1024][1024]
__device__ __half g_woT[DIM_ * INNER_];             // Wo^T [768][512]
__device__ __half g_qbuf[BNQ * INNER_];             // q*scale fp16
__device__ __half g_kvp[(size_t)BTM * 1024];        // K|V proj fp16 (128MB)
__device__ __half g_att[BNQ * INNER_];              // attn out fp16

// ---------------- helpers ----------------
__device__ __forceinline__ uint32_t packh2(float lo, float hi) {
    uint32_t r;
    asm("cvt.rn.f16x2.f32 %0, %1, %2;" : "=r"(r) : "f"(hi), "f"(lo));
    return r;
}

__device__ __forceinline__ void mma16(float c[4], const uint32_t a[4],
                                      uint32_t b0, uint32_t b1) {
    asm volatile("mma.sync.aligned.m16n8k16.row.col.f32.f16.f16.f32 "
        "{%0,%1,%2,%3}, {%4,%5,%6,%7}, {%8,%9}, {%0,%1,%2,%3};"
        : "+f"(c[0]), "+f"(c[1]), "+f"(c[2]), "+f"(c[3])
        : "r"(a[0]), "r"(a[1]), "r"(a[2]), "r"(a[3]), "r"(b0), "r"(b1));
}

__device__ __forceinline__ void cpa(uint32_t dst, const void* src) {
    asm volatile("cp.async.cg.shared.global [%0], [%1], 16;" :: "r"(dst), "l"(src));
}
#define CP_COMMIT asm volatile("cp.async.commit_group;")
#define CP_WAIT1  asm volatile("cp.async.wait_group 1;")
#define CP_WAIT2  asm volatile("cp.async.wait_group 2;")

__device__ __forceinline__ uint32_t smem_u32(const void* p) {
    return (uint32_t)__cvta_generic_to_shared(p);
}

#define LDSM_T(r0, r1, r2, r3, addr) \
    asm volatile("ldmatrix.sync.aligned.m8n8.x4.trans.shared.b16 {%0,%1,%2,%3}, [%4];" \
                 : "=r"(r0), "=r"(r1), "=r"(r2), "=r"(r3) : "r"(addr))

// ---------------- fused LayerNorm + fp16 convert ----------------
template <int RL>
__global__ __launch_bounds__(256) void ln_conv(const float* __restrict__ X,
                                               const float* __restrict__ gam,
                                               const float* __restrict__ bet,
                                               __half* __restrict__ Y) {
    const int row = blockIdx.x;
    const int i = threadIdx.x;
    const bool act = i < RL / 4;
    float4 v = make_float4(0.f, 0.f, 0.f, 0.f);
    if (act) v = reinterpret_cast<const float4*>(X + (size_t)row * RL)[i];
    float s  = (v.x + v.y) + (v.z + v.w);
    float ss = v.x * v.x + v.y * v.y + v.z * v.z + v.w * v.w;
    #pragma unroll
    for (int o = 16; o; o >>= 1) {
        s  += __shfl_xor_sync(0xffffffffu, s, o);
        ss += __shfl_xor_sync(0xffffffffu, ss, o);
    }
    __shared__ float sh[16];
    __shared__ float st[2];
    const int w = i >> 5, l = i & 31;
    if (l == 0) { sh[w] = s; sh[w + 8] = ss; }
    __syncthreads();
    if (i == 0) {
        float S = 0.f, SS = 0.f;
        #pragma unroll
        for (int k = 0; k < 8; k++) { S += sh[k]; SS += sh[k + 8]; }
        const float m = S / (float)RL;
        st[0] = m;
        st[1] = rsqrtf(SS / (float)RL - m * m + LN_EPS);
    }
    __syncthreads();
    if (act) {
        const float m = st[0], r = st[1];
        const float4 gv = reinterpret_cast<const float4*>(gam)[i];
        const float4 bv = reinterpret_cast<const float4*>(bet)[i];
        uint2 o;
        o.x = packh2((v.x - m) * r * gv.x + bv.x, (v.y - m) * r * gv.y + bv.y);
        o.y = packh2((v.z - m) * r * gv.z + bv.z, (v.w - m) * r * gv.w + bv.w);
        *reinterpret_cast<uint2*>(Y + (size_t)row * RL + i * 4) = o;
    }
}

// ---------------- weight transpose: W[K][N] fp32 -> Wt[N][K] fp16 ----------------
__global__ __launch_bounds__(256) void wconvT(const float* __restrict__ W,
                                              __half* __restrict__ Wt,
                                              int K, int N) {
    __shared__ __half t[32][33];
    const int tx = threadIdx.x, ty = threadIdx.y;
    const int k0 = blockIdx.y * 32, n0 = blockIdx.x * 32;
    #pragma unroll
    for (int i = 0; i < 4; i++)
        t[ty + i * 8][tx] = __float2half_rn(W[(size_t)(k0 + ty + i * 8) * N + n0 + tx]);
    __syncthreads();
    #pragma unroll
    for (int i = 0; i < 4; i++)
        Wt[(size_t)(n0 + ty + i * 8) * K + k0 + tx] = t[tx][ty + i * 8];
}

// ---------------- pipelined fp16 GEMM: C[M,N] = (A[M,K] @ Bt[N,K]^T) * alpha ----
// 128x128x32 tiles, 3-stage cp.async, 8 warps (4x2), warp tile 32x64.
#define SAH 40                        // smem row stride (halves)
#define ASTG_H (128 * SAH)            // 5120 halves per A tile
#define STAGE_H (2 * ASTG_H)          // 10240 halves per stage (A+B)
#define GEMM_SMEM (3 * STAGE_H * 2)   // 61440 B

template <bool OTF>
__global__ __launch_bounds__(256, 2) void gemm_f16(
    const __half* __restrict__ A, const __half* __restrict__ Bt,
    void* __restrict__ Cv, int N, int K, float alpha) {
    extern __shared__ __half smh[];
    const uint32_t s_b = smem_u32(smh);

    const int tid = threadIdx.x;
    const int warp = tid >> 5, lane = tid & 31;
    const int g = lane >> 2, q = lane & 3;
    const int wm = (warp >> 1) * 32;
    const int wn = (warp & 1) * 64;
    const int bm0 = blockIdx.y * 128;
    const int bn0 = blockIdx.x * 128;
    const __half* Ab = A + (size_t)bm0 * K;
    const __half* Bb = Bt + (size_t)bn0 * K;

    auto issue = [&](int stage, int kt) {
        const uint32_t base = s_b + stage * STAGE_H * 2;
        #pragma unroll
        for (int c = 0; c < 2; c++) {
            const int cid = tid + c * 256;
            const int row = cid >> 2, c8 = (cid & 3) * 8;
            cpa(base + (uint32_t)(row * SAH + c8) * 2,
                Ab + (size_t)row * K + kt + c8);
            cpa(base + ASTG_H * 2 + (uint32_t)(row * SAH + c8) * 2,
                Bb + (size_t)row * K + kt + c8);
        }
    };

    float acc[2][8][4];
    #pragma unroll
    for (int mt = 0; mt < 2; mt++)
        #pragma unroll
        for (int nt = 0; nt < 8; nt++)
            #pragma unroll
            for (int i = 0; i < 4; i++) acc[mt][nt][i] = 0.f;

    const int nk = K / 32;
    issue(0, 0);  CP_COMMIT;
    issue(1, 32); CP_COMMIT;

    for (int t = 0; t < nk; t++) {
        if (t + 2 < nk) issue((t + 2) % 3, (t + 2) * 32);
        CP_COMMIT;
        CP_WAIT2;
        __syncthreads();
        const __half* cA = smh + (t % 3) * STAGE_H;
        const __half* cB = cA + ASTG_H;
        #pragma unroll
        for (int kk = 0; kk < 32; kk += 16) {
            uint32_t af[2][4];
            #pragma unroll
            for (int mt = 0; mt < 2; mt++) {
                const __half* p = cA + (wm + mt * 16 + g) * SAH + kk + 2 * q;
                af[mt][0] = *reinterpret_cast<const uint32_t*>(p);
                af[mt][1] = *reinterpret_cast<const uint32_t*>(p + 8 * SAH);
                af[mt][2] = *reinterpret_cast<const uint32_t*>(p + 8);
                af[mt][3] = *reinterpret_cast<const uint32_t*>(p + 8 * SAH + 8);
            }
            #pragma unroll
            for (int nt = 0; nt < 8; nt++) {
                const __half* p = cB + (wn + nt * 8 + g) * SAH + kk + 2 * q;
                const uint32_t b0 = *reinterpret_cast<const uint32_t*>(p);
                const uint32_t b1 = *reinterpret_cast<const uint32_t*>(p + 8);
                mma16(acc[0][nt], af[0], b0, b1);
                mma16(acc[1][nt], af[1], b0, b1);
            }
        }
        __syncthreads();
    }

    #pragma unroll
    for (int mt = 0; mt < 2; mt++)
        #pragma unroll
        for (int nt = 0; nt < 8; nt++) {
            const int r0 = bm0 + wm + mt * 16 + g;
            const int c0 = bn0 + wn + nt * 8 + 2 * q;
            if (OTF) {
                __half* C = (__half*)Cv;
                *reinterpret_cast<uint32_t*>(C + (size_t)r0 * N + c0) =
                    packh2(acc[mt][nt][0] * alpha, acc[mt][nt][1] * alpha);
                *reinterpret_cast<uint32_t*>(C + (size_t)(r0 + 8) * N + c0) =
                    packh2(acc[mt][nt][2] * alpha, acc[mt][nt][3] * alpha);
            } else {
                float* C = (float*)Cv;
                *reinterpret_cast<float2*>(C + (size_t)r0 * N + c0) =
                    make_float2(acc[mt][nt][0] * alpha, acc[mt][nt][1] * alpha);
                *reinterpret_cast<float2*>(C + (size_t)(r0 + 8) * N + c0) =
                    make_float2(acc[mt][nt][2] * alpha, acc[mt][nt][3] * alpha);
            }
        }
}

// ---------------- flash attention (fp16, P in registers, ldmatrix.trans for V) --
#define JC   64
#define KST  88                         // K/V smem row stride (halves), 176B
#define TILE_H (JC * KST)               // 5632 halves per tile
#define KOFF(buf) ((buf) * TILE_H)
#define VOFF(buf) (2 * TILE_H + (buf) * TILE_H)
#define ATT_SMEM (4 * TILE_H * 2)       // 45056 B

__global__ __launch_bounds__(256, 1) void attention_kernel(
    const __half* __restrict__ Q, const __half* __restrict__ KV,
    __half* __restrict__ O) {
    extern __shared__ __half smh[];
    const uint32_t s_b = smem_u32(smh);

    const int bh = blockIdx.x;
    const int b = bh >> 3, h = bh & 7;
    const int q0 = blockIdx.y * 128;
    const int tid = threadIdx.x, warp = tid >> 5, lane = tid & 31;
    const int g = lane >> 2, q = lane & 3;

    const __half* Kg = KV + (size_t)(b * TM_) * 1024 + h * DH_;
    const __half* Vg = Kg + INNER_;

    auto issue = [&](int buf, int j0) {
        #pragma unroll
        for (int p = 0; p < 2; p++) {
            const int cid = tid + p * 256;
            const int jj = cid >> 3, c8 = (cid & 7) * 8;
            cpa(s_b + (uint32_t)(KOFF(buf) + jj * KST + c8) * 2,
                Kg + (size_t)(j0 + jj) * 1024 + c8);
            cpa(s_b + (uint32_t)(VOFF(buf) + jj * KST + c8) * 2,
                Vg + (size_t)(j0 + jj) * 1024 + c8);
        }
    };

    // Q fragments resident (pre-scaled fp16)
    uint32_t qa[4][4];
    const int qrow0 = b * NQ_ + q0 + warp * 16;
    const __half* Qb = Q + (size_t)qrow0 * INNER_ + h * DH_;
    #pragma unroll
    for (int ks = 0; ks < 4; ks++) {
        const __half* p = Qb + (size_t)g * INNER_ + ks * 16 + 2 * q;
        qa[ks][0] = *reinterpret_cast<const uint32_t*>(p);
        qa[ks][1] = *reinterpret_cast<const uint32_t*>(p + 8 * INNER_);
        qa[ks][2] = *reinterpret_cast<const uint32_t*>(p + 8);
        qa[ks][3] = *reinterpret_cast<const uint32_t*>(p + 8 * INNER_ + 8);
    }

    float oacc[8][4];
    #pragma unroll
    for (int nt = 0; nt < 8; nt++)
        #pragma unroll
        for (int i = 0; i < 4; i++) oacc[nt][i] = 0.f;
    float mrow0 = -1e30f, mrow1 = -1e30f;
    float lrow0 = 0.f, lrow1 = 0.f;

    // per-lane ldmatrix base offset within a V tile (halves)
    const int lm_row = lane & 15;
    const int lm_col = (lane >> 4) * 8;

    const int NC = TM_ / JC;
    issue(0, 0); CP_COMMIT;

    for (int jc = 0; jc < NC; jc++) {
        const int buf = jc & 1;
        if (jc + 1 < NC) issue(buf ^ 1, (jc + 1) * JC);
        CP_COMMIT;
        CP_WAIT1;
        __syncthreads();

        const __half* Ks = smh + KOFF(buf);

        // S = Q @ K^T  (warp: 16 x 64)
        float sacc[8][4];
        #pragma unroll
        for (int nt = 0; nt < 8; nt++)
            #pragma unroll
            for (int i = 0; i < 4; i++) sacc[nt][i] = 0.f;
        #pragma unroll
        for (int ks = 0; ks < 4; ks++) {
            #pragma unroll
            for (int nt = 0; nt < 8; nt++) {
                const __half* p = Ks + (nt * 8 + g) * KST + ks * 16 + 2 * q;
                const uint32_t b0 = *reinterpret_cast<const uint32_t*>(p);
                const uint32_t b1 = *reinterpret_cast<const uint32_t*>(p + 8);
                mma16(sacc[nt], qa[ks], b0, b1);
            }
        }

        // online softmax (rows g, g+8; quad owns cols 2q,2q+1 per tile)
        float mn0 = mrow0, mn1 = mrow1;
        #pragma unroll
        for (int nt = 0; nt < 8; nt++) {
            mn0 = fmaxf(mn0, fmaxf(sacc[nt][0], sacc[nt][1]));
            mn1 = fmaxf(mn1, fmaxf(sacc[nt][2], sacc[nt][3]));
        }
        #pragma unroll
        for (int o = 1; o < 4; o <<= 1) {
            mn0 = fmaxf(mn0, __shfl_xor_sync(0xffffffffu, mn0, o));
            mn1 = fmaxf(mn1, __shfl_xor_sync(0xffffffffu, mn1, o));
        }
        const float al0 = __expf(mrow0 - mn0);
        const float al1 = __expf(mrow1 - mn1);
        float ls0 = 0.f, ls1 = 0.f;
        #pragma unroll
        for (int nt = 0; nt < 8; nt++) {
            sacc[nt][0] = __expf(sacc[nt][0] - mn0);
            sacc[nt][1] = __expf(sacc[nt][1] - mn0);
            sacc[nt][2] = __expf(sacc[nt][2] - mn1);
            sacc[nt][3] = __expf(sacc[nt][3] - mn1);
            ls0 += sacc[nt][0] + sacc[nt][1];
            ls1 += sacc[nt][2] + sacc[nt][3];
        }
        #pragma unroll
        for (int o = 1; o < 4; o <<= 1) {
            ls0 += __shfl_xor_sync(0xffffffffu, ls0, o);
            ls1 += __shfl_xor_sync(0xffffffffu, ls1, o);
        }
        lrow0 = lrow0 * al0 + ls0;
        lrow1 = lrow1 * al1 + ls1;
        mrow0 = mn0; mrow1 = mn1;
        #pragma unroll
        for (int nt = 0; nt < 8; nt++) {
            oacc[nt][0] *= al0; oacc[nt][1] *= al0;
            oacc[nt][2] *= al1; oacc[nt][3] *= al1;
        }

        // pack P into fp16 A-fragments (registers, no smem round-trip)
        uint32_t pa[4][4];
        #pragma unroll
        for (int ks = 0; ks < 4; ks++) {
            pa[ks][0] = packh2(sacc[2 * ks][0],     sacc[2 * ks][1]);
            pa[ks][1] = packh2(sacc[2 * ks][2],     sacc[2 * ks][3]);
            pa[ks][2] = packh2(sacc[2 * ks + 1][0], sacc[2 * ks + 1][1]);
            pa[ks][3] = packh2(sacc[2 * ks + 1][2], sacc[2 * ks + 1][3]);
        }

        // O += P @ V   (V^T fragments via ldmatrix.trans)
        const uint32_t vbase =
            s_b + (uint32_t)(VOFF(buf) + lm_row * KST + lm_col) * 2;
        #pragma unroll
        for (int ks = 0; ks < 4; ks++) {
            #pragma unroll
            for (int dg = 0; dg < 4; dg++) {
                uint32_t v0, v1, v2, v3;
                LDSM_T(v0, v1, v2, v3,
                       vbase + (uint32_t)(ks * 16 * KST + dg * 16) * 2);
                mma16(oacc[dg * 2],     pa[ks], v0, v1);
                mma16(oacc[dg * 2 + 1], pa[ks], v2, v3);
            }
        }
        __syncthreads();
    }

    // epilogue: normalize, fp16 out
    const float inv0 = 1.f / lrow0;
    const float inv1 = 1.f / lrow1;
    __half* Ob = O + (size_t)qrow0 * INNER_ + h * DH_;
    #pragma unroll
    for (int nt = 0; nt < 8; nt++) {
        const int c0 = nt * 8 + 2 * q;
        *reinterpret_cast<uint32_t*>(Ob + (size_t)g * INNER_ + c0) =
            packh2(oacc[nt][0] * inv0, oacc[nt][1] * inv0);
        *reinterpret_cast<uint32_t*>(Ob + (size_t)(g + 8) * INNER_ + c0) =
            packh2(oacc[nt][2] * inv1, oacc[nt][3] * inv1);
    }
}

// ---------------- launch ----------------
extern "C" void kernel_launch(void* const* d_in, const int* in_sizes, int n_in,
                              void* d_out, int out_size) {
    const float* x    = (const float*)d_in[0];
    const float* k_v  = (const float*)d_in[1];
    const float* g_q  = (const float*)d_in[2];
    const float* b_q  = (const float*)d_in[3];
    const float* g_kv = (const float*)d_in[4];
    const float* b_kv = (const float*)d_in[5];
    const float* Wq   = (const float*)d_in[6];
    const float* Wkv  = (const float*)d_in[7];
    const float* Wo   = (const float*)d_in[8];
    float* out = (float*)d_out;

    __half *xn, *kvn, *wqT, *wkvT, *woT, *qbuf, *kvp, *att;
    cudaGetSymbolAddress((void**)&xn,   g_xn);
    cudaGetSymbolAddress((void**)&kvn,  g_kvn);
    cudaGetSymbolAddress((void**)&wqT,  g_wqT);
    cudaGetSymbolAddress((void**)&wkvT, g_wkvT);
    cudaGetSymbolAddress((void**)&woT,  g_woT);
    cudaGetSymbolAddress((void**)&qbuf, g_qbuf);
    cudaGetSymbolAddress((void**)&kvp,  g_kvp);
    cudaGetSymbolAddress((void**)&att,  g_att);

    cudaFuncSetAttribute(gemm_f16<true>,
                         cudaFuncAttributeMaxDynamicSharedMemorySize, GEMM_SMEM);
    cudaFuncSetAttribute(gemm_f16<false>,
                         cudaFuncAttributeMaxDynamicSharedMemorySize, GEMM_SMEM);
    cudaFuncSetAttribute(attention_kernel,
                         cudaFuncAttributeMaxDynamicSharedMemorySize, ATT_SMEM);

    // 0,1: LayerNorm + fp16 convert
    ln_conv<KVD_><<<BTM, 256>>>(k_v, g_kv, b_kv, kvn);
    ln_conv<DIM_><<<BNQ, 256>>>(x, g_q, b_q, xn);

    // 2: Wkv^T
    wconvT<<<dim3(1024 / 32, KVD_ / 32), dim3(32, 8)>>>(Wkv, wkvT, KVD_, 1024);

    // 3 (profiled slot): kv projection  [65536,1024] = kvn @ WkvT^T
    gemm_f16<true><<<dim3(1024 / 128, BTM / 128), 256, GEMM_SMEM>>>(
        kvn, wkvT, kvp, 1024, KVD_, 1.f);

    // 4,5: remaining weight transposes
    wconvT<<<dim3(INNER_ / 32, DIM_ / 32), dim3(32, 8)>>>(Wq, wqT, DIM_, INNER_);
    wconvT<<<dim3(DIM_ / 32, INNER_ / 32), dim3(32, 8)>>>(Wo, woT, INNER_, DIM_);

    // 6: q = LN(x) @ Wq * scale
    gemm_f16<true><<<dim3(INNER_ / 128, BNQ / 128), 256, GEMM_SMEM>>>(
        xn, wqT, qbuf, INNER_, DIM_, 0.125f);

    // 7: flash attention
    attention_kernel<<<dim3(BB * HH, NQ_ / 128), 256, ATT_SMEM>>>(qbuf, kvp, att);

    // 8: out = att @ Wo  (fp32 output)
    gemm_f16<false><<<dim3(DIM_ / 128, BNQ / 128), 256, GEMM_SMEM>>>(
        att, woT, out, DIM_, INNER_, 1.f);
}

// round 5
// speedup vs baseline: 3.4241x; 1.0174x over previous
#include <cuda_runtime.h>
#include <cuda_fp16.h>
#include <cstdint>

// ---------------- problem constants ----------------
#define BB     8
#define NQ_    256
#define DIM_   768
#define KVD_   1024
#define HH     8
#define DH_    64
#define INNER_ 512
#define TM_    8192
#define BNQ    2048
#define BTM    65536
#define LN_EPS 1e-5f

// ---------------- scratch (device globals) ----------------
__device__ __half g_xn[BNQ * DIM_];
__device__ __half g_kvn[(size_t)BTM * KVD_];
__device__ __half g_wqT[INNER_ * DIM_];
__device__ __half g_wkvT[1024 * KVD_];
__device__ __half g_woT[DIM_ * INNER_];
__device__ __half g_qbuf[BNQ * INNER_];
__device__ __half g_kvp[(size_t)BTM * 1024];
__device__ __half g_att[BNQ * INNER_];

// ---------------- helpers ----------------
__device__ __forceinline__ uint32_t packh2(float lo, float hi) {
    uint32_t r;
    asm("cvt.rn.f16x2.f32 %0, %1, %2;" : "=r"(r) : "f"(hi), "f"(lo));
    return r;
}

__device__ __forceinline__ void mma16(float c[4], const uint32_t a[4],
                                      uint32_t b0, uint32_t b1) {
    asm volatile("mma.sync.aligned.m16n8k16.row.col.f32.f16.f16.f32 "
        "{%0,%1,%2,%3}, {%4,%5,%6,%7}, {%8,%9}, {%0,%1,%2,%3};"
        : "+f"(c[0]), "+f"(c[1]), "+f"(c[2]), "+f"(c[3])
        : "r"(a[0]), "r"(a[1]), "r"(a[2]), "r"(a[3]), "r"(b0), "r"(b1));
}

__device__ __forceinline__ void cpa(uint32_t dst, const void* src) {
    asm volatile("cp.async.cg.shared.global [%0], [%1], 16;" :: "r"(dst), "l"(src));
}
#define CP_COMMIT asm volatile("cp.async.commit_group;")
#define CP_WAIT1  asm volatile("cp.async.wait_group 1;")
#define CP_WAIT2  asm volatile("cp.async.wait_group 2;")

__device__ __forceinline__ uint32_t smem_u32(const void* p) {
    return (uint32_t)__cvta_generic_to_shared(p);
}

#define LDSM_X4(r0, r1, r2, r3, addr) \
    asm volatile("ldmatrix.sync.aligned.m8n8.x4.shared.b16 {%0,%1,%2,%3}, [%4];" \
                 : "=r"(r0), "=r"(r1), "=r"(r2), "=r"(r3) : "r"(addr))
#define LDSM_T(r0, r1, r2, r3, addr) \
    asm volatile("ldmatrix.sync.aligned.m8n8.x4.trans.shared.b16 {%0,%1,%2,%3}, [%4];" \
                 : "=r"(r0), "=r"(r1), "=r"(r2), "=r"(r3) : "r"(addr))

// ---------------- fused LayerNorm + fp16 convert ----------------
template <int RL>
__global__ __launch_bounds__(256) void ln_conv(const float* __restrict__ X,
                                               const float* __restrict__ gam,
                                               const float* __restrict__ bet,
                                               __half* __restrict__ Y) {
    const int row = blockIdx.x;
    const int i = threadIdx.x;
    const bool act = i < RL / 4;
    float4 v = make_float4(0.f, 0.f, 0.f, 0.f);
    if (act) v = reinterpret_cast<const float4*>(X + (size_t)row * RL)[i];
    float s  = (v.x + v.y) + (v.z + v.w);
    float ss = v.x * v.x + v.y * v.y + v.z * v.z + v.w * v.w;
    #pragma unroll
    for (int o = 16; o; o >>= 1) {
        s  += __shfl_xor_sync(0xffffffffu, s, o);
        ss += __shfl_xor_sync(0xffffffffu, ss, o);
    }
    __shared__ float sh[16];
    __shared__ float st[2];
    const int w = i >> 5, l = i & 31;
    if (l == 0) { sh[w] = s; sh[w + 8] = ss; }
    __syncthreads();
    if (i == 0) {
        float S = 0.f, SS = 0.f;
        #pragma unroll
        for (int k = 0; k < 8; k++) { S += sh[k]; SS += sh[k + 8]; }
        const float m = S / (float)RL;
        st[0] = m;
        st[1] = rsqrtf(SS / (float)RL - m * m + LN_EPS);
    }
    __syncthreads();
    if (act) {
        const float m = st[0], r = st[1];
        const float4 gv = reinterpret_cast<const float4*>(gam)[i];
        const float4 bv = reinterpret_cast<const float4*>(bet)[i];
        uint2 o;
        o.x = packh2((v.x - m) * r * gv.x + bv.x, (v.y - m) * r * gv.y + bv.y);
        o.y = packh2((v.z - m) * r * gv.z + bv.z, (v.w - m) * r * gv.w + bv.w);
        *reinterpret_cast<uint2*>(Y + (size_t)row * RL + i * 4) = o;
    }
}

// ---------------- weight transpose ----------------
__global__ __launch_bounds__(256) void wconvT(const float* __restrict__ W,
                                              __half* __restrict__ Wt,
                                              int K, int N) {
    __shared__ __half t[32][33];
    const int tx = threadIdx.x, ty = threadIdx.y;
    const int k0 = blockIdx.y * 32, n0 = blockIdx.x * 32;
    #pragma unroll
    for (int i = 0; i < 4; i++)
        t[ty + i * 8][tx] = __float2half_rn(W[(size_t)(k0 + ty + i * 8) * N + n0 + tx]);
    __syncthreads();
    #pragma unroll
    for (int i = 0; i < 4; i++)
        Wt[(size_t)(n0 + ty + i * 8) * K + k0 + tx] = t[tx][ty + i * 8];
}

// ---------------- pipelined fp16 GEMM (ldmatrix feed) ----------------
// C[M,N] = (A[M,K] @ Bt[N,K]^T) * alpha; 128x128x32 tiles, 3-stage cp.async.
#define SAH 40
#define ASTG_H (128 * SAH)
#define STAGE_H (2 * ASTG_H)
#define GEMM_SMEM (3 * STAGE_H * 2)   // 61440 B

template <bool OTF>
__global__ __launch_bounds__(256, 2) void gemm_f16(
    const __half* __restrict__ A, const __half* __restrict__ Bt,
    void* __restrict__ Cv, int N, int K, float alpha) {
    extern __shared__ __half smh[];
    const uint32_t s_b = smem_u32(smh);

    const int tid = threadIdx.x;
    const int warp = tid >> 5, lane = tid & 31;
    const int g = lane >> 2, q = lane & 3;
    const int wm = (warp >> 1) * 32;
    const int wn = (warp & 1) * 64;
    const int bm0 = blockIdx.y * 128;
    const int bn0 = blockIdx.x * 128;
    const __half* Ab = A + (size_t)bm0 * K;
    const __half* Bb = Bt + (size_t)bn0 * K;

    // ldmatrix per-lane offsets (halves)
    const int lmA = (lane & 15) * SAH + ((lane >> 4) << 3);          // A: rows, k-group
    const int lmB = (((lane >> 4) << 3) + (lane & 7)) * SAH + (((lane >> 3) & 1) << 3);

    auto issue = [&](int stage, int kt) {
        const uint32_t base = s_b + stage * STAGE_H * 2;
        #pragma unroll
        for (int c = 0; c < 2; c++) {
            const int cid = tid + c * 256;
            const int row = cid >> 2, c8 = (cid & 3) * 8;
            cpa(base + (uint32_t)(row * SAH + c8) * 2,
                Ab + (size_t)row * K + kt + c8);
            cpa(base + ASTG_H * 2 + (uint32_t)(row * SAH + c8) * 2,
                Bb + (size_t)row * K + kt + c8);
        }
    };

    float acc[2][8][4];
    #pragma unroll
    for (int mt = 0; mt < 2; mt++)
        #pragma unroll
        for (int nt = 0; nt < 8; nt++)
            #pragma unroll
            for (int i = 0; i < 4; i++) acc[mt][nt][i] = 0.f;

    const int nk = K / 32;
    issue(0, 0);  CP_COMMIT;
    issue(1, 32); CP_COMMIT;

    for (int t = 0; t < nk; t++) {
        if (t + 2 < nk) issue((t + 2) % 3, (t + 2) * 32);
        CP_COMMIT;
        CP_WAIT2;
        __syncthreads();
        const uint32_t cAb = s_b + ((t % 3) * STAGE_H) * 2;
        const uint32_t cBb = cAb + ASTG_H * 2;
        #pragma unroll
        for (int kk = 0; kk < 32; kk += 16) {
            uint32_t af[2][4];
            #pragma unroll
            for (int mt = 0; mt < 2; mt++)
                LDSM_X4(af[mt][0], af[mt][1], af[mt][2], af[mt][3],
                        cAb + (uint32_t)((wm + mt * 16) * SAH + kk + lmA) * 2);
            #pragma unroll
            for (int p = 0; p < 4; p++) {
                uint32_t b0, b1, b2, b3;
                LDSM_X4(b0, b1, b2, b3,
                        cBb + (uint32_t)((wn + p * 16) * SAH + kk + lmB) * 2);
                mma16(acc[0][2 * p],     af[0], b0, b1);
                mma16(acc[1][2 * p],     af[1], b0, b1);
                mma16(acc[0][2 * p + 1], af[0], b2, b3);
                mma16(acc[1][2 * p + 1], af[1], b2, b3);
            }
        }
        __syncthreads();
    }

    #pragma unroll
    for (int mt = 0; mt < 2; mt++)
        #pragma unroll
        for (int nt = 0; nt < 8; nt++) {
            const int r0 = bm0 + wm + mt * 16 + g;
            const int c0 = bn0 + wn + nt * 8 + 2 * q;
            if (OTF) {
                __half* C = (__half*)Cv;
                *reinterpret_cast<uint32_t*>(C + (size_t)r0 * N + c0) =
                    packh2(acc[mt][nt][0] * alpha, acc[mt][nt][1] * alpha);
                *reinterpret_cast<uint32_t*>(C + (size_t)(r0 + 8) * N + c0) =
                    packh2(acc[mt][nt][2] * alpha, acc[mt][nt][3] * alpha);
            } else {
                float* C = (float*)Cv;
                *reinterpret_cast<float2*>(C + (size_t)r0 * N + c0) =
                    make_float2(acc[mt][nt][0] * alpha, acc[mt][nt][1] * alpha);
                *reinterpret_cast<float2*>(C + (size_t)(r0 + 8) * N + c0) =
                    make_float2(acc[mt][nt][2] * alpha, acc[mt][nt][3] * alpha);
            }
        }
}

// ---------------- flash attention (ldmatrix K feed, P in regs) ----------------
#define JC   64
#define KST  88
#define TILE_H (JC * KST)
#define KOFF(buf) ((buf) * TILE_H)
#define VOFF(buf) (2 * TILE_H + (buf) * TILE_H)
#define ATT_SMEM (4 * TILE_H * 2)

__global__ __launch_bounds__(256, 1) void attention_kernel(
    const __half* __restrict__ Q, const __half* __restrict__ KV,
    __half* __restrict__ O) {
    extern __shared__ __half smh[];
    const uint32_t s_b = smem_u32(smh);

    const int bh = blockIdx.x;
    const int b = bh >> 3, h = bh & 7;
    const int q0 = blockIdx.y * 128;
    const int tid = threadIdx.x, warp = tid >> 5, lane = tid & 31;
    const int g = lane >> 2, q = lane & 3;

    const __half* Kg = KV + (size_t)(b * TM_) * 1024 + h * DH_;
    const __half* Vg = Kg + INNER_;

    auto issue = [&](int buf, int j0) {
        #pragma unroll
        for (int p = 0; p < 2; p++) {
            const int cid = tid + p * 256;
            const int jj = cid >> 3, c8 = (cid & 7) * 8;
            cpa(s_b + (uint32_t)(KOFF(buf) + jj * KST + c8) * 2,
                Kg + (size_t)(j0 + jj) * 1024 + c8);
            cpa(s_b + (uint32_t)(VOFF(buf) + jj * KST + c8) * 2,
                Vg + (size_t)(j0 + jj) * 1024 + c8);
        }
    };

    uint32_t qa[4][4];
    const int qrow0 = b * NQ_ + q0 + warp * 16;
    const __half* Qb = Q + (size_t)qrow0 * INNER_ + h * DH_;
    #pragma unroll
    for (int ks = 0; ks < 4; ks++) {
        const __half* p = Qb + (size_t)g * INNER_ + ks * 16 + 2 * q;
        qa[ks][0] = *reinterpret_cast<const uint32_t*>(p);
        qa[ks][1] = *reinterpret_cast<const uint32_t*>(p + 8 * INNER_);
        qa[ks][2] = *reinterpret_cast<const uint32_t*>(p + 8);
        qa[ks][3] = *reinterpret_cast<const uint32_t*>(p + 8 * INNER_ + 8);
    }

    float oacc[8][4];
    #pragma unroll
    for (int nt = 0; nt < 8; nt++)
        #pragma unroll
        for (int i = 0; i < 4; i++) oacc[nt][i] = 0.f;
    float mrow0 = -1e30f, mrow1 = -1e30f;
    float lrow0 = 0.f, lrow1 = 0.f;

    const int lmB = (((lane >> 4) << 3) + (lane & 7)) * KST + (((lane >> 3) & 1) << 3);
    const int lm_row = lane & 15;
    const int lm_col = (lane >> 4) * 8;

    const int NC = TM_ / JC;
    issue(0, 0); CP_COMMIT;

    for (int jc = 0; jc < NC; jc++) {
        const int buf = jc & 1;
        if (jc + 1 < NC) issue(buf ^ 1, (jc + 1) * JC);
        CP_COMMIT;
        CP_WAIT1;
        __syncthreads();

        // S = Q @ K^T  (warp: 16 x 64), K fragments via ldmatrix.x4
        float sacc[8][4];
        #pragma unroll
        for (int nt = 0; nt < 8; nt++)
            #pragma unroll
            for (int i = 0; i < 4; i++) sacc[nt][i] = 0.f;
        const uint32_t kb = s_b + (uint32_t)KOFF(buf) * 2;
        #pragma unroll
        for (int ks = 0; ks < 4; ks++) {
            #pragma unroll
            for (int p = 0; p < 4; p++) {
                uint32_t b0, b1, b2, b3;
                LDSM_X4(b0, b1, b2, b3,
                        kb + (uint32_t)(p * 16 * KST + ks * 16 + lmB) * 2);
                mma16(sacc[2 * p],     qa[ks], b0, b1);
                mma16(sacc[2 * p + 1], qa[ks], b2, b3);
            }
        }

        // online softmax
        float mn0 = mrow0, mn1 = mrow1;
        #pragma unroll
        for (int nt = 0; nt < 8; nt++) {
            mn0 = fmaxf(mn0, fmaxf(sacc[nt][0], sacc[nt][1]));
            mn1 = fmaxf(mn1, fmaxf(sacc[nt][2], sacc[nt][3]));
        }
        #pragma unroll
        for (int o = 1; o < 4; o <<= 1) {
            mn0 = fmaxf(mn0, __shfl_xor_sync(0xffffffffu, mn0, o));
            mn1 = fmaxf(mn1, __shfl_xor_sync(0xffffffffu, mn1, o));
        }
        const float al0 = __expf(mrow0 - mn0);
        const float al1 = __expf(mrow1 - mn1);
        float ls0 = 0.f, ls1 = 0.f;
        #pragma unroll
        for (int nt = 0; nt < 8; nt++) {
            sacc[nt][0] = __expf(sacc[nt][0] - mn0);
            sacc[nt][1] = __expf(sacc[nt][1] - mn0);
            sacc[nt][2] = __expf(sacc[nt][2] - mn1);
            sacc[nt][3] = __expf(sacc[nt][3] - mn1);
            ls0 += sacc[nt][0] + sacc[nt][1];
            ls1 += sacc[nt][2] + sacc[nt][3];
        }
        #pragma unroll
        for (int o = 1; o < 4; o <<= 1) {
            ls0 += __shfl_xor_sync(0xffffffffu, ls0, o);
            ls1 += __shfl_xor_sync(0xffffffffu, ls1, o);
        }
        lrow0 = lrow0 * al0 + ls0;
        lrow1 = lrow1 * al1 + ls1;
        mrow0 = mn0; mrow1 = mn1;
        #pragma unroll
        for (int nt = 0; nt < 8; nt++) {
            oacc[nt][0] *= al0; oacc[nt][1] *= al0;
            oacc[nt][2] *= al1; oacc[nt][3] *= al1;
        }

        // pack P into fp16 A-fragments
        uint32_t pa[4][4];
        #pragma unroll
        for (int ks = 0; ks < 4; ks++) {
            pa[ks][0] = packh2(sacc[2 * ks][0],     sacc[2 * ks][1]);
            pa[ks][1] = packh2(sacc[2 * ks][2],     sacc[2 * ks][3]);
            pa[ks][2] = packh2(sacc[2 * ks + 1][0], sacc[2 * ks + 1][1]);
            pa[ks][3] = packh2(sacc[2 * ks + 1][2], sacc[2 * ks + 1][3]);
        }

        // O += P @ V  (V^T via ldmatrix.trans)
        const uint32_t vbase =
            s_b + (uint32_t)(VOFF(buf) + lm_row * KST + lm_col) * 2;
        #pragma unroll
        for (int ks = 0; ks < 4; ks++) {
            #pragma unroll
            for (int dg = 0; dg < 4; dg++) {
                uint32_t v0, v1, v2, v3;
                LDSM_T(v0, v1, v2, v3,
                       vbase + (uint32_t)(ks * 16 * KST + dg * 16) * 2);
                mma16(oacc[dg * 2],     pa[ks], v0, v1);
                mma16(oacc[dg * 2 + 1], pa[ks], v2, v3);
            }
        }
        __syncthreads();
    }

    const float inv0 = 1.f / lrow0;
    const float inv1 = 1.f / lrow1;
    __half* Ob = O + (size_t)qrow0 * INNER_ + h * DH_;
    #pragma unroll
    for (int nt = 0; nt < 8; nt++) {
        const int c0 = nt * 8 + 2 * q;
        *reinterpret_cast<uint32_t*>(Ob + (size_t)g * INNER_ + c0) =
            packh2(oacc[nt][0] * inv0, oacc[nt][1] * inv0);
        *reinterpret_cast<uint32_t*>(Ob + (size_t)(g + 8) * INNER_ + c0) =
            packh2(oacc[nt][2] * inv1, oacc[nt][3] * inv1);
    }
}

// ---------------- launch ----------------
extern "C" void kernel_launch(void* const* d_in, const int* in_sizes, int n_in,
                              void* d_out, int out_size) {
    const float* x    = (const float*)d_in[0];
    const float* k_v  = (const float*)d_in[1];
    const float* g_q  = (const float*)d_in[2];
    const float* b_q  = (const float*)d_in[3];
    const float* g_kv = (const float*)d_in[4];
    const float* b_kv = (const float*)d_in[5];
    const float* Wq   = (const float*)d_in[6];
    const float* Wkv  = (const float*)d_in[7];
    const float* Wo   = (const float*)d_in[8];
    float* out = (float*)d_out;

    __half *xn, *kvn, *wqT, *wkvT, *woT, *qbuf, *kvp, *att;
    cudaGetSymbolAddress((void**)&xn,   g_xn);
    cudaGetSymbolAddress((void**)&kvn,  g_kvn);
    cudaGetSymbolAddress((void**)&wqT,  g_wqT);
    cudaGetSymbolAddress((void**)&wkvT, g_wkvT);
    cudaGetSymbolAddress((void**)&woT,  g_woT);
    cudaGetSymbolAddress((void**)&qbuf, g_qbuf);
    cudaGetSymbolAddress((void**)&kvp,  g_kvp);
    cudaGetSymbolAddress((void**)&att,  g_att);

    cudaFuncSetAttribute(gemm_f16<true>,
                         cudaFuncAttributeMaxDynamicSharedMemorySize, GEMM_SMEM);
    cudaFuncSetAttribute(gemm_f16<false>,
                         cudaFuncAttributeMaxDynamicSharedMemorySize, GEMM_SMEM);
    cudaFuncSetAttribute(attention_kernel,
                         cudaFuncAttributeMaxDynamicSharedMemorySize, ATT_SMEM);

    // 0,1: LayerNorm + fp16 convert
    ln_conv<KVD_><<<BTM, 256>>>(k_v, g_kv, b_kv, kvn);
    ln_conv<DIM_><<<BNQ, 256>>>(x, g_q, b_q, xn);

    // 2: Wkv^T
    wconvT<<<dim3(1024 / 32, KVD_ / 32), dim3(32, 8)>>>(Wkv, wkvT, KVD_, 1024);

    // 3 (profiled slot): kv projection
    gemm_f16<true><<<dim3(1024 / 128, BTM / 128), 256, GEMM_SMEM>>>(
        kvn, wkvT, kvp, 1024, KVD_, 1.f);

    // 4,5: remaining weight transposes
    wconvT<<<dim3(INNER_ / 32, DIM_ / 32), dim3(32, 8)>>>(Wq, wqT, DIM_, INNER_);
    wconvT<<<dim3(DIM_ / 32, INNER_ / 32), dim3(32, 8)>>>(Wo, woT, INNER_, DIM_);

    // 6: q proj
    gemm_f16<true><<<dim3(INNER_ / 128, BNQ / 128), 256, GEMM_SMEM>>>(
        xn, wqT, qbuf, INNER_, DIM_, 0.125f);

    // 7: flash attention
    attention_kernel<<<dim3(BB * HH, NQ_ / 128), 256, ATT_SMEM>>>(qbuf, kvp, att);

    // 8: out proj (fp32 output)
    gemm_f16<false><<<dim3(DIM_ / 128, BNQ / 128), 256, GEMM_SMEM>>>(
        att, woT, out, DIM_, INNER_, 1.f);
}

// round 6
// speedup vs baseline: 3.7319x; 1.0899x over previous
#include <cuda_runtime.h>
#include <cuda_fp16.h>
#include <cstdint>

// ---------------- problem constants ----------------
#define BB     8
#define NQ_    256
#define DIM_   768
#define KVD_   1024
#define HH     8
#define DH_    64
#define INNER_ 512
#define TM_    8192
#define BNQ    2048
#define BTM    65536
#define LN_EPS 1e-5f

// ---------------- scratch (device globals) ----------------
__device__ __half g_xn[BNQ * DIM_];
__device__ __half g_kvn[(size_t)BTM * KVD_];
__device__ __half g_wqT[INNER_ * DIM_];
__device__ __half g_wkvT[1024 * KVD_];
__device__ __half g_woT[DIM_ * INNER_];
__device__ __half g_qbuf[BNQ * INNER_];
__device__ __half g_kvp[(size_t)BTM * 1024];
__device__ __half g_att[BNQ * INNER_];

// ---------------- helpers ----------------
__device__ __forceinline__ uint32_t packh2(float lo, float hi) {
    uint32_t r;
    asm("cvt.rn.f16x2.f32 %0, %1, %2;" : "=r"(r) : "f"(hi), "f"(lo));
    return r;
}

__device__ __forceinline__ void mma16(float c[4], const uint32_t a[4],
                                      uint32_t b0, uint32_t b1) {
    asm volatile("mma.sync.aligned.m16n8k16.row.col.f32.f16.f16.f32 "
        "{%0,%1,%2,%3}, {%4,%5,%6,%7}, {%8,%9}, {%0,%1,%2,%3};"
        : "+f"(c[0]), "+f"(c[1]), "+f"(c[2]), "+f"(c[3])
        : "r"(a[0]), "r"(a[1]), "r"(a[2]), "r"(a[3]), "r"(b0), "r"(b1));
}

__device__ __forceinline__ void cpa(uint32_t dst, const void* src) {
    asm volatile("cp.async.cg.shared.global [%0], [%1], 16;" :: "r"(dst), "l"(src));
}
#define CP_COMMIT asm volatile("cp.async.commit_group;")
#define CP_WAIT1  asm volatile("cp.async.wait_group 1;")
#define CP_WAIT2  asm volatile("cp.async.wait_group 2;")

__device__ __forceinline__ uint32_t smem_u32(const void* p) {
    return (uint32_t)__cvta_generic_to_shared(p);
}

#define LDSM_X4(r0, r1, r2, r3, addr) \
    asm volatile("ldmatrix.sync.aligned.m8n8.x4.shared.b16 {%0,%1,%2,%3}, [%4];" \
                 : "=r"(r0), "=r"(r1), "=r"(r2), "=r"(r3) : "r"(addr))
#define LDSM_T(r0, r1, r2, r3, addr) \
    asm volatile("ldmatrix.sync.aligned.m8n8.x4.trans.shared.b16 {%0,%1,%2,%3}, [%4];" \
                 : "=r"(r0), "=r"(r1), "=r"(r2), "=r"(r3) : "r"(addr))

// ---------------- fused LayerNorm + fp16 convert ----------------
template <int RL>
__global__ __launch_bounds__(256) void ln_conv(const float* __restrict__ X,
                                               const float* __restrict__ gam,
                                               const float* __restrict__ bet,
                                               __half* __restrict__ Y) {
    const int row = blockIdx.x;
    const int i = threadIdx.x;
    const bool act = i < RL / 4;
    float4 v = make_float4(0.f, 0.f, 0.f, 0.f);
    if (act) v = reinterpret_cast<const float4*>(X + (size_t)row * RL)[i];
    float s  = (v.x + v.y) + (v.z + v.w);
    float ss = v.x * v.x + v.y * v.y + v.z * v.z + v.w * v.w;
    #pragma unroll
    for (int o = 16; o; o >>= 1) {
        s  += __shfl_xor_sync(0xffffffffu, s, o);
        ss += __shfl_xor_sync(0xffffffffu, ss, o);
    }
    __shared__ float sh[16];
    __shared__ float st[2];
    const int w = i >> 5, l = i & 31;
    if (l == 0) { sh[w] = s; sh[w + 8] = ss; }
    __syncthreads();
    if (i == 0) {
        float S = 0.f, SS = 0.f;
        #pragma unroll
        for (int k = 0; k < 8; k++) { S += sh[k]; SS += sh[k + 8]; }
        const float m = S / (float)RL;
        st[0] = m;
        st[1] = rsqrtf(SS / (float)RL - m * m + LN_EPS);
    }
    __syncthreads();
    if (act) {
        const float m = st[0], r = st[1];
        const float4 gv = reinterpret_cast<const float4*>(gam)[i];
        const float4 bv = reinterpret_cast<const float4*>(bet)[i];
        uint2 o;
        o.x = packh2((v.x - m) * r * gv.x + bv.x, (v.y - m) * r * gv.y + bv.y);
        o.y = packh2((v.z - m) * r * gv.z + bv.z, (v.w - m) * r * gv.w + bv.w);
        *reinterpret_cast<uint2*>(Y + (size_t)row * RL + i * 4) = o;
    }
}

// ---------------- weight transpose ----------------
__global__ __launch_bounds__(256) void wconvT(const float* __restrict__ W,
                                              __half* __restrict__ Wt,
                                              int K, int N) {
    __shared__ __half t[32][33];
    const int tx = threadIdx.x, ty = threadIdx.y;
    const int k0 = blockIdx.y * 32, n0 = blockIdx.x * 32;
    #pragma unroll
    for (int i = 0; i < 4; i++)
        t[ty + i * 8][tx] = __float2half_rn(W[(size_t)(k0 + ty + i * 8) * N + n0 + tx]);
    __syncthreads();
    #pragma unroll
    for (int i = 0; i < 4; i++)
        Wt[(size_t)(n0 + ty + i * 8) * K + k0 + tx] = t[tx][ty + i * 8];
}

// ================= BIG GEMM: 256x128 CTA tile, 64x64 warp tile, 4-stage, 1 sync ====
#define SAH 40
#define BG_A_H (256 * SAH)                  // 10240 halves
#define BG_B_H (128 * SAH)                  // 5120 halves
#define BG_STG_H (BG_A_H + BG_B_H)          // 15360 halves / stage
#define BG_SMEM (4 * BG_STG_H * 2)          // 122880 B

__global__ __launch_bounds__(256, 1) void gemm_f16_big(
    const __half* __restrict__ A, const __half* __restrict__ Bt,
    __half* __restrict__ C, int N, int K) {
    extern __shared__ __half smh[];
    const uint32_t s_b = smem_u32(smh);

    const int tid = threadIdx.x;
    const int warp = tid >> 5, lane = tid & 31;
    const int g = lane >> 2, q = lane & 3;
    const int wm = (warp >> 1) * 64;        // warp row offset (4 warps down)
    const int wn = (warp & 1) * 64;         // warp col offset (2 warps across)
    const int bm0 = blockIdx.y * 256;
    const int bn0 = blockIdx.x * 128;
    const __half* Ab = A + (size_t)bm0 * K;
    const __half* Bb = Bt + (size_t)bn0 * K;

    const int lmA = (lane & 15) * SAH + ((lane >> 4) << 3);
    const int lmB = (((lane >> 4) << 3) + (lane & 7)) * SAH + (((lane >> 3) & 1) << 3);

    auto issue = [&](int stage, int kt) {
        const uint32_t base = s_b + stage * BG_STG_H * 2;
        #pragma unroll
        for (int c = 0; c < 4; c++) {        // A: 256 rows x 32 halves
            const int cid = tid + c * 256;
            const int row = cid >> 2, c8 = (cid & 3) * 8;
            cpa(base + (uint32_t)(row * SAH + c8) * 2,
                Ab + (size_t)row * K + kt + c8);
        }
        #pragma unroll
        for (int c = 0; c < 2; c++) {        // B: 128 rows x 32 halves
            const int cid = tid + c * 256;
            const int row = cid >> 2, c8 = (cid & 3) * 8;
            cpa(base + BG_A_H * 2 + (uint32_t)(row * SAH + c8) * 2,
                Bb + (size_t)row * K + kt + c8);
        }
    };

    float acc[4][8][4];
    #pragma unroll
    for (int mt = 0; mt < 4; mt++)
        #pragma unroll
        for (int nt = 0; nt < 8; nt++)
            #pragma unroll
            for (int i = 0; i < 4; i++) acc[mt][nt][i] = 0.f;

    const int nk = K / 32;
    issue(0, 0);  CP_COMMIT;
    issue(1, 32); CP_COMMIT;
    issue(2, 64); CP_COMMIT;

    for (int t = 0; t < nk; t++) {
        CP_WAIT2;
        __syncthreads();
        const uint32_t cAb = s_b + ((t & 3) * BG_STG_H) * 2;
        const uint32_t cBb = cAb + BG_A_H * 2;
        #pragma unroll
        for (int kk = 0; kk < 32; kk += 16) {
            uint32_t af[4][4];
            #pragma unroll
            for (int mt = 0; mt < 4; mt++)
                LDSM_X4(af[mt][0], af[mt][1], af[mt][2], af[mt][3],
                        cAb + (uint32_t)((wm + mt * 16) * SAH + kk + lmA) * 2);
            #pragma unroll
            for (int p = 0; p < 4; p++) {
                uint32_t b0, b1, b2, b3;
                LDSM_X4(b0, b1, b2, b3,
                        cBb + (uint32_t)((wn + p * 16) * SAH + kk + lmB) * 2);
                #pragma unroll
                for (int mt = 0; mt < 4; mt++) {
                    mma16(acc[mt][2 * p],     af[mt], b0, b1);
                    mma16(acc[mt][2 * p + 1], af[mt], b2, b3);
                }
            }
        }
        if (t + 3 < nk) issue((t + 3) & 3, (t + 3) * 32);
        CP_COMMIT;
    }

    #pragma unroll
    for (int mt = 0; mt < 4; mt++)
        #pragma unroll
        for (int nt = 0; nt < 8; nt++) {
            const int r0 = bm0 + wm + mt * 16 + g;
            const int c0 = bn0 + wn + nt * 8 + 2 * q;
            *reinterpret_cast<uint32_t*>(C + (size_t)r0 * N + c0) =
                packh2(acc[mt][nt][0], acc[mt][nt][1]);
            *reinterpret_cast<uint32_t*>(C + (size_t)(r0 + 8) * N + c0) =
                packh2(acc[mt][nt][2], acc[mt][nt][3]);
        }
}

// ---------------- small pipelined fp16 GEMM (128x128x32, 3-stage) ----------------
#define ASTG_H (128 * SAH)
#define STAGE_H (2 * ASTG_H)
#define GEMM_SMEM (3 * STAGE_H * 2)   // 61440 B

template <bool OTF>
__global__ __launch_bounds__(256, 2) void gemm_f16(
    const __half* __restrict__ A, const __half* __restrict__ Bt,
    void* __restrict__ Cv, int N, int K, float alpha) {
    extern __shared__ __half smh[];
    const uint32_t s_b = smem_u32(smh);

    const int tid = threadIdx.x;
    const int warp = tid >> 5, lane = tid & 31;
    const int g = lane >> 2, q = lane & 3;
    const int wm = (warp >> 1) * 32;
    const int wn = (warp & 1) * 64;
    const int bm0 = blockIdx.y * 128;
    const int bn0 = blockIdx.x * 128;
    const __half* Ab = A + (size_t)bm0 * K;
    const __half* Bb = Bt + (size_t)bn0 * K;

    const int lmA = (lane & 15) * SAH + ((lane >> 4) << 3);
    const int lmB = (((lane >> 4) << 3) + (lane & 7)) * SAH + (((lane >> 3) & 1) << 3);

    auto issue = [&](int stage, int kt) {
        const uint32_t base = s_b + stage * STAGE_H * 2;
        #pragma unroll
        for (int c = 0; c < 2; c++) {
            const int cid = tid + c * 256;
            const int row = cid >> 2, c8 = (cid & 3) * 8;
            cpa(base + (uint32_t)(row * SAH + c8) * 2,
                Ab + (size_t)row * K + kt + c8);
            cpa(base + ASTG_H * 2 + (uint32_t)(row * SAH + c8) * 2,
                Bb + (size_t)row * K + kt + c8);
        }
    };

    float acc[2][8][4];
    #pragma unroll
    for (int mt = 0; mt < 2; mt++)
        #pragma unroll
        for (int nt = 0; nt < 8; nt++)
            #pragma unroll
            for (int i = 0; i < 4; i++) acc[mt][nt][i] = 0.f;

    const int nk = K / 32;
    issue(0, 0);  CP_COMMIT;
    issue(1, 32); CP_COMMIT;

    for (int t = 0; t < nk; t++) {
        if (t + 2 < nk) issue((t + 2) % 3, (t + 2) * 32);
        CP_COMMIT;
        CP_WAIT2;
        __syncthreads();
        const uint32_t cAb = s_b + ((t % 3) * STAGE_H) * 2;
        const uint32_t cBb = cAb + ASTG_H * 2;
        #pragma unroll
        for (int kk = 0; kk < 32; kk += 16) {
            uint32_t af[2][4];
            #pragma unroll
            for (int mt = 0; mt < 2; mt++)
                LDSM_X4(af[mt][0], af[mt][1], af[mt][2], af[mt][3],
                        cAb + (uint32_t)((wm + mt * 16) * SAH + kk + lmA) * 2);
            #pragma unroll
            for (int p = 0; p < 4; p++) {
                uint32_t b0, b1, b2, b3;
                LDSM_X4(b0, b1, b2, b3,
                        cBb + (uint32_t)((wn + p * 16) * SAH + kk + lmB) * 2);
                mma16(acc[0][2 * p],     af[0], b0, b1);
                mma16(acc[1][2 * p],     af[1], b0, b1);
                mma16(acc[0][2 * p + 1], af[0], b2, b3);
                mma16(acc[1][2 * p + 1], af[1], b2, b3);
            }
        }
        __syncthreads();
    }

    #pragma unroll
    for (int mt = 0; mt < 2; mt++)
        #pragma unroll
        for (int nt = 0; nt < 8; nt++) {
            const int r0 = bm0 + wm + mt * 16 + g;
            const int c0 = bn0 + wn + nt * 8 + 2 * q;
            if (OTF) {
                __half* C = (__half*)Cv;
                *reinterpret_cast<uint32_t*>(C + (size_t)r0 * N + c0) =
                    packh2(acc[mt][nt][0] * alpha, acc[mt][nt][1] * alpha);
                *reinterpret_cast<uint32_t*>(C + (size_t)(r0 + 8) * N + c0) =
                    packh2(acc[mt][nt][2] * alpha, acc[mt][nt][3] * alpha);
            } else {
                float* C = (float*)Cv;
                *reinterpret_cast<float2*>(C + (size_t)r0 * N + c0) =
                    make_float2(acc[mt][nt][0] * alpha, acc[mt][nt][1] * alpha);
                *reinterpret_cast<float2*>(C + (size_t)(r0 + 8) * N + c0) =
                    make_float2(acc[mt][nt][2] * alpha, acc[mt][nt][3] * alpha);
            }
        }
}

// ---------------- flash attention (unchanged from R5) ----------------
#define JC   64
#define KST  88
#define TILE_H (JC * KST)
#define KOFF(buf) ((buf) * TILE_H)
#define VOFF(buf) (2 * TILE_H + (buf) * TILE_H)
#define ATT_SMEM (4 * TILE_H * 2)

__global__ __launch_bounds__(256, 1) void attention_kernel(
    const __half* __restrict__ Q, const __half* __restrict__ KV,
    __half* __restrict__ O) {
    extern __shared__ __half smh[];
    const uint32_t s_b = smem_u32(smh);

    const int bh = blockIdx.x;
    const int b = bh >> 3, h = bh & 7;
    const int q0 = blockIdx.y * 128;
    const int tid = threadIdx.x, warp = tid >> 5, lane = tid & 31;
    const int g = lane >> 2, q = lane & 3;

    const __half* Kg = KV + (size_t)(b * TM_) * 1024 + h * DH_;
    const __half* Vg = Kg + INNER_;

    auto issue = [&](int buf, int j0) {
        #pragma unroll
        for (int p = 0; p < 2; p++) {
            const int cid = tid + p * 256;
            const int jj = cid >> 3, c8 = (cid & 7) * 8;
            cpa(s_b + (uint32_t)(KOFF(buf) + jj * KST + c8) * 2,
                Kg + (size_t)(j0 + jj) * 1024 + c8);
            cpa(s_b + (uint32_t)(VOFF(buf) + jj * KST + c8) * 2,
                Vg + (size_t)(j0 + jj) * 1024 + c8);
        }
    };

    uint32_t qa[4][4];
    const int qrow0 = b * NQ_ + q0 + warp * 16;
    const __half* Qb = Q + (size_t)qrow0 * INNER_ + h * DH_;
    #pragma unroll
    for (int ks = 0; ks < 4; ks++) {
        const __half* p = Qb + (size_t)g * INNER_ + ks * 16 + 2 * q;
        qa[ks][0] = *reinterpret_cast<const uint32_t*>(p);
        qa[ks][1] = *reinterpret_cast<const uint32_t*>(p + 8 * INNER_);
        qa[ks][2] = *reinterpret_cast<const uint32_t*>(p + 8);
        qa[ks][3] = *reinterpret_cast<const uint32_t*>(p + 8 * INNER_ + 8);
    }

    float oacc[8][4];
    #pragma unroll
    for (int nt = 0; nt < 8; nt++)
        #pragma unroll
        for (int i = 0; i < 4; i++) oacc[nt][i] = 0.f;
    float mrow0 = -1e30f, mrow1 = -1e30f;
    float lrow0 = 0.f, lrow1 = 0.f;

    const int lmB = (((lane >> 4) << 3) + (lane & 7)) * KST + (((lane >> 3) & 1) << 3);
    const int lm_row = lane & 15;
    const int lm_col = (lane >> 4) * 8;

    const int NC = TM_ / JC;
    issue(0, 0); CP_COMMIT;

    for (int jc = 0; jc < NC; jc++) {
        const int buf = jc & 1;
        if (jc + 1 < NC) issue(buf ^ 1, (jc + 1) * JC);
        CP_COMMIT;
        CP_WAIT1;
        __syncthreads();

        float sacc[8][4];
        #pragma unroll
        for (int nt = 0; nt < 8; nt++)
            #pragma unroll
            for (int i = 0; i < 4; i++) sacc[nt][i] = 0.f;
        const uint32_t kb = s_b + (uint32_t)KOFF(buf) * 2;
        #pragma unroll
        for (int ks = 0; ks < 4; ks++) {
            #pragma unroll
            for (int p = 0; p < 4; p++) {
                uint32_t b0, b1, b2, b3;
                LDSM_X4(b0, b1, b2, b3,
                        kb + (uint32_t)(p * 16 * KST + ks * 16 + lmB) * 2);
                mma16(sacc[2 * p],     qa[ks], b0, b1);
                mma16(sacc[2 * p + 1], qa[ks], b2, b3);
            }
        }

        float mn0 = mrow0, mn1 = mrow1;
        #pragma unroll
        for (int nt = 0; nt < 8; nt++) {
            mn0 = fmaxf(mn0, fmaxf(sacc[nt][0], sacc[nt][1]));
            mn1 = fmaxf(mn1, fmaxf(sacc[nt][2], sacc[nt][3]));
        }
        #pragma unroll
        for (int o = 1; o < 4; o <<= 1) {
            mn0 = fmaxf(mn0, __shfl_xor_sync(0xffffffffu, mn0, o));
            mn1 = fmaxf(mn1, __shfl_xor_sync(0xffffffffu, mn1, o));
        }
        const float al0 = __expf(mrow0 - mn0);
        const float al1 = __expf(mrow1 - mn1);
        float ls0 = 0.f, ls1 = 0.f;
        #pragma unroll
        for (int nt = 0; nt < 8; nt++) {
            sacc[nt][0] = __expf(sacc[nt][0] - mn0);
            sacc[nt][1] = __expf(sacc[nt][1] - mn0);
            sacc[nt][2] = __expf(sacc[nt][2] - mn1);
            sacc[nt][3] = __expf(sacc[nt][3] - mn1);
            ls0 += sacc[nt][0] + sacc[nt][1];
            ls1 += sacc[nt][2] + sacc[nt][3];
        }
        #pragma unroll
        for (int o = 1; o < 4; o <<= 1) {
            ls0 += __shfl_xor_sync(0xffffffffu, ls0, o);
            ls1 += __shfl_xor_sync(0xffffffffu, ls1, o);
        }
        lrow0 = lrow0 * al0 + ls0;
        lrow1 = lrow1 * al1 + ls1;
        mrow0 = mn0; mrow1 = mn1;
        #pragma unroll
        for (int nt = 0; nt < 8; nt++) {
            oacc[nt][0] *= al0; oacc[nt][1] *= al0;
            oacc[nt][2] *= al1; oacc[nt][3] *= al1;
        }

        uint32_t pa[4][4];
        #pragma unroll
        for (int ks = 0; ks < 4; ks++) {
            pa[ks][0] = packh2(sacc[2 * ks][0],     sacc[2 * ks][1]);
            pa[ks][1] = packh2(sacc[2 * ks][2],     sacc[2 * ks][3]);
            pa[ks][2] = packh2(sacc[2 * ks + 1][0], sacc[2 * ks + 1][1]);
            pa[ks][3] = packh2(sacc[2 * ks + 1][2], sacc[2 * ks + 1][3]);
        }

        const uint32_t vbase =
            s_b + (uint32_t)(VOFF(buf) + lm_row * KST + lm_col) * 2;
        #pragma unroll
        for (int ks = 0; ks < 4; ks++) {
            #pragma unroll
            for (int dg = 0; dg < 4; dg++) {
                uint32_t v0, v1, v2, v3;
                LDSM_T(v0, v1, v2, v3,
                       vbase + (uint32_t)(ks * 16 * KST + dg * 16) * 2);
                mma16(oacc[dg * 2],     pa[ks], v0, v1);
                mma16(oacc[dg * 2 + 1], pa[ks], v2, v3);
            }
        }
        __syncthreads();
    }

    const float inv0 = 1.f / lrow0;
    const float inv1 = 1.f / lrow1;
    __half* Ob = O + (size_t)qrow0 * INNER_ + h * DH_;
    #pragma unroll
    for (int nt = 0; nt < 8; nt++) {
        const int c0 = nt * 8 + 2 * q;
        *reinterpret_cast<uint32_t*>(Ob + (size_t)g * INNER_ + c0) =
            packh2(oacc[nt][0] * inv0, oacc[nt][1] * inv0);
        *reinterpret_cast<uint32_t*>(Ob + (size_t)(g + 8) * INNER_ + c0) =
            packh2(oacc[nt][2] * inv1, oacc[nt][3] * inv1);
    }
}

// ---------------- launch ----------------
extern "C" void kernel_launch(void* const* d_in, const int* in_sizes, int n_in,
                              void* d_out, int out_size) {
    const float* x    = (const float*)d_in[0];
    const float* k_v  = (const float*)d_in[1];
    const float* g_q  = (const float*)d_in[2];
    const float* b_q  = (const float*)d_in[3];
    const float* g_kv = (const float*)d_in[4];
    const float* b_kv = (const float*)d_in[5];
    const float* Wq   = (const float*)d_in[6];
    const float* Wkv  = (const float*)d_in[7];
    const float* Wo   = (const float*)d_in[8];
    float* out = (float*)d_out;

    __half *xn, *kvn, *wqT, *wkvT, *woT, *qbuf, *kvp, *att;
    cudaGetSymbolAddress((void**)&xn,   g_xn);
    cudaGetSymbolAddress((void**)&kvn,  g_kvn);
    cudaGetSymbolAddress((void**)&wqT,  g_wqT);
    cudaGetSymbolAddress((void**)&wkvT, g_wkvT);
    cudaGetSymbolAddress((void**)&woT,  g_woT);
    cudaGetSymbolAddress((void**)&qbuf, g_qbuf);
    cudaGetSymbolAddress((void**)&kvp,  g_kvp);
    cudaGetSymbolAddress((void**)&att,  g_att);

    cudaFuncSetAttribute(gemm_f16<true>,
                         cudaFuncAttributeMaxDynamicSharedMemorySize, GEMM_SMEM);
    cudaFuncSetAttribute(gemm_f16<false>,
                         cudaFuncAttributeMaxDynamicSharedMemorySize, GEMM_SMEM);
    cudaFuncSetAttribute(gemm_f16_big,
                         cudaFuncAttributeMaxDynamicSharedMemorySize, BG_SMEM);
    cudaFuncSetAttribute(attention_kernel,
                         cudaFuncAttributeMaxDynamicSharedMemorySize, ATT_SMEM);

    // 0,1: LayerNorm + fp16 convert
    ln_conv<KVD_><<<BTM, 256>>>(k_v, g_kv, b_kv, kvn);
    ln_conv<DIM_><<<BNQ, 256>>>(x, g_q, b_q, xn);

    // 2: Wkv^T
    wconvT<<<dim3(1024 / 32, KVD_ / 32), dim3(32, 8)>>>(Wkv, wkvT, KVD_, 1024);

    // 3 (profiled slot): kv projection, big-tile GEMM
    gemm_f16_big<<<dim3(1024 / 128, BTM / 256), 256, BG_SMEM>>>(
        kvn, wkvT, kvp, 1024, KVD_);

    // 4,5: remaining weight transposes
    wconvT<<<dim3(INNER_ / 32, DIM_ / 32), dim3(32, 8)>>>(Wq, wqT, DIM_, INNER_);
    wconvT<<<dim3(DIM_ / 32, INNER_ / 32), dim3(32, 8)>>>(Wo, woT, INNER_, DIM_);

    // 6: q proj
    gemm_f16<true><<<dim3(INNER_ / 128, BNQ / 128), 256, GEMM_SMEM>>>(
        xn, wqT, qbuf, INNER_, DIM_, 0.125f);

    // 7: flash attention
    attention_kernel<<<dim3(BB * HH, NQ_ / 128), 256, ATT_SMEM>>>(qbuf, kvp, att);

    // 8: out proj (fp32 output)
    gemm_f16<false><<<dim3(DIM_ / 128, BNQ / 128), 256, GEMM_SMEM>>>(
        att, woT, out, DIM_, INNER_, 1.f);
}